// round 3
// baseline (speedup 1.0000x reference)
#include <cuda_runtime.h>
#include <cstdint>

// Fixed problem shapes
#define B_  1
#define E_  128
#define L_  256
#define H_  12
#define DH_ 64
#define D_  768          // H_*DH_
#define D3_ 2304         // 3*D_
#define N_  32768        // B_*E_*L_
#define EPSLN 1e-5f
#define NEGV  -10000.0f

// Scratch (allocations are forbidden -> device globals)
__device__ float g_qkv[(size_t)N_ * D3_];   // 302 MB
__device__ float g_tmp[(size_t)N_ * D_];    // 100 MB

// ---------------------------------------------------------------------------
// SGEMM (NT, fused bias): C[n,m] = sum_k A[n,k]*B[m,k] + bias[m]
// A:[N,K] row-major, B:[M,K] row-major. BM=BN=128, BK=8, TM=TN=8, 256 threads
// ---------------------------------------------------------------------------
__global__ __launch_bounds__(256) void sgemm_nt_bias(
    const float* __restrict__ A, const float* __restrict__ B,
    const float* __restrict__ bias, float* __restrict__ C,
    int N, int M, int K)
{
    __shared__ float As[8][128];
    __shared__ float Bs[8][128];

    const int tid  = threadIdx.x;
    const int bRow = blockIdx.y;      // N tile
    const int bCol = blockIdx.x;      // M tile

    const float* Ablk = A + (size_t)bRow * 128 * K;
    const float* Bblk = B + (size_t)bCol * 128 * K;

    const int lr = tid >> 1;          // 0..127 loader row
    const int lk = (tid & 1) * 4;     // 0 or 4  loader k
    const int tr = (tid >> 4) * 8;    // 0..120  compute row
    const int tc = (tid & 15) * 8;    // 0..120  compute col

    float acc[8][8];
#pragma unroll
    for (int i = 0; i < 8; i++)
#pragma unroll
        for (int j = 0; j < 8; j++) acc[i][j] = 0.f;

    for (int k0 = 0; k0 < K; k0 += 8) {
        float4 a4 = *(const float4*)(Ablk + (size_t)lr * K + k0 + lk);
        float4 b4 = *(const float4*)(Bblk + (size_t)lr * K + k0 + lk);
        __syncthreads();              // prior compute done before overwrite
        As[lk + 0][lr] = a4.x; As[lk + 1][lr] = a4.y;
        As[lk + 2][lr] = a4.z; As[lk + 3][lr] = a4.w;
        Bs[lk + 0][lr] = b4.x; Bs[lk + 1][lr] = b4.y;
        Bs[lk + 2][lr] = b4.z; Bs[lk + 3][lr] = b4.w;
        __syncthreads();
#pragma unroll
        for (int kk = 0; kk < 8; kk++) {
            float ra[8], rb[8];
#pragma unroll
            for (int i = 0; i < 8; i++) ra[i] = As[kk][tr + i];
#pragma unroll
            for (int j = 0; j < 8; j++) rb[j] = Bs[kk][tc + j];
#pragma unroll
            for (int i = 0; i < 8; i++)
#pragma unroll
                for (int j = 0; j < 8; j++) acc[i][j] += ra[i] * rb[j];
        }
    }

    const int cbase = bCol * 128 + tc;
    float bi[8];
#pragma unroll
    for (int j = 0; j < 8; j++) bi[j] = bias[cbase + j];
#pragma unroll
    for (int i = 0; i < 8; i++) {
        float* Crow = C + (size_t)(bRow * 128 + tr + i) * M + cbase;
#pragma unroll
        for (int j = 0; j < 8; j++) Crow[j] = acc[i][j] + bi[j];
    }
}

// ---------------------------------------------------------------------------
// Row attention: for each (e,h), attend over L=256 keys.
// block = 256 threads, one query per thread, online softmax, K/V/Q in smem.
// qkv layout: [N, 3D] with q|k|v at col offsets 0/768/1536; n = e*256 + i.
// mask is int32 (harness has no bool dtype).
// ---------------------------------------------------------------------------
__global__ __launch_bounds__(256, 1) void attn_row(
    const float* __restrict__ qkv, const int* __restrict__ mask,
    float* __restrict__ out)
{
    extern __shared__ float sm[];
    float* Qs   = sm;                   // 256*65 (pad 65 avoids LDS conflicts)
    float* Ks   = Qs + 256 * 65;        // 256*64
    float* Vs   = Ks + 256 * 64;        // 256*64
    float* negs = Vs + 256 * 64;        // 256

    const int h = blockIdx.x, e = blockIdx.y;
    const int tid = threadIdx.x;
    const size_t baseQ = (size_t)e * 256 * D3_ + h * 64;

    for (int idx = tid; idx < 256 * 64; idx += 256) {
        int j = idx >> 6, d = idx & 63;
        size_t rb = baseQ + (size_t)j * D3_ + d;
        Qs[j * 65 + d] = qkv[rb] * 0.125f;       // DH^-0.5
        Ks[idx]        = qkv[rb + 768];
        Vs[idx]        = qkv[rb + 1536];
    }
    if (tid < 256) negs[tid] = mask[e * 256 + tid] ? NEGV : 0.f;
    __syncthreads();

    const int i = tid;
    float q[64];
#pragma unroll
    for (int d = 0; d < 64; d++) q[d] = Qs[i * 65 + d];

    float m = -1e30f, l = 0.f, acc[64];
#pragma unroll
    for (int d = 0; d < 64; d++) acc[d] = 0.f;

    for (int j = 0; j < 256; j++) {
        const float* kj = Ks + j * 64;
        float s = 0.f;
#pragma unroll
        for (int d = 0; d < 64; d++) s += q[d] * kj[d];
        s += negs[j];
        const float* vj = Vs + j * 64;
        if (s <= m) {
            float p = __expf(s - m);
            l += p;
#pragma unroll
            for (int d = 0; d < 64; d++) acc[d] += p * vj[d];
        } else {
            float corr = __expf(m - s);
            m = s;
            l = l * corr + 1.f;
#pragma unroll
            for (int d = 0; d < 64; d++) acc[d] = acc[d] * corr + vj[d];
        }
    }
    const float inv = 1.f / l;
    const size_t ob = ((size_t)e * 256 + i) * D_ + h * 64;
#pragma unroll
    for (int d = 0; d < 64; d++) out[ob + d] = acc[d] * inv;
}

// ---------------------------------------------------------------------------
// Column attention: for each (l,h), attend over E=128 keys.
// block = 128 threads, one query per thread. n = e*256 + l.
// Mask: key j (an E index) masked iff padding_mask[j*256 + l].
// ---------------------------------------------------------------------------
__global__ __launch_bounds__(128, 1) void attn_col(
    const float* __restrict__ qkv, const int* __restrict__ mask,
    float* __restrict__ out)
{
    extern __shared__ float sm[];
    float* Qs   = sm;                   // 128*65
    float* Ks   = Qs + 128 * 65;        // 128*64
    float* Vs   = Ks + 128 * 64;        // 128*64
    float* negs = Vs + 128 * 64;        // 128

    const int h = blockIdx.x, l = blockIdx.y;
    const int tid = threadIdx.x;

    for (int idx = tid; idx < 128 * 64; idx += 128) {
        int j = idx >> 6, d = idx & 63;
        size_t rb = ((size_t)j * 256 + l) * D3_ + h * 64 + d;
        Qs[j * 65 + d] = qkv[rb] * 0.125f;
        Ks[idx]        = qkv[rb + 768];
        Vs[idx]        = qkv[rb + 1536];
    }
    if (tid < 128) negs[tid] = mask[tid * 256 + l] ? NEGV : 0.f;
    __syncthreads();

    const int i = tid;
    float q[64];
#pragma unroll
    for (int d = 0; d < 64; d++) q[d] = Qs[i * 65 + d];

    float m = -1e30f, lsum = 0.f, acc[64];
#pragma unroll
    for (int d = 0; d < 64; d++) acc[d] = 0.f;

    for (int j = 0; j < 128; j++) {
        const float* kj = Ks + j * 64;
        float s = 0.f;
#pragma unroll
        for (int d = 0; d < 64; d++) s += q[d] * kj[d];
        s += negs[j];
        const float* vj = Vs + j * 64;
        if (s <= m) {
            float p = __expf(s - m);
            lsum += p;
#pragma unroll
            for (int d = 0; d < 64; d++) acc[d] += p * vj[d];
        } else {
            float corr = __expf(m - s);
            m = s;
            lsum = lsum * corr + 1.f;
#pragma unroll
            for (int d = 0; d < 64; d++) acc[d] = acc[d] * corr + vj[d];
        }
    }
    const float inv = 1.f / lsum;
    const size_t ob = ((size_t)i * 256 + l) * D_ + h * 64;
#pragma unroll
    for (int d = 0; d < 64; d++) out[ob + d] = acc[d] * inv;
}

// ---------------------------------------------------------------------------
// out = LayerNorm(a + b) * g + beta   — one block per row of 768, 256 threads
// Safe for out == a (row fully read into regs before any write).
// ---------------------------------------------------------------------------
__global__ __launch_bounds__(256) void add_ln(
    const float* __restrict__ a, const float* __restrict__ b,
    const float* __restrict__ g, const float* __restrict__ beta,
    float* __restrict__ out)
{
    const int n = blockIdx.x, tid = threadIdx.x;
    const size_t base = (size_t)n * D_;

    float v[3], s = 0.f, ss = 0.f;
#pragma unroll
    for (int t = 0; t < 3; t++) {
        int c = tid + t * 256;
        float x = a[base + c] + b[base + c];
        v[t] = x; s += x; ss += x * x;
    }
#pragma unroll
    for (int off = 16; off > 0; off >>= 1) {
        s  += __shfl_xor_sync(0xffffffffu, s,  off);
        ss += __shfl_xor_sync(0xffffffffu, ss, off);
    }
    __shared__ float sh_s[8], sh_ss[8];
    const int wid = tid >> 5, lane = tid & 31;
    if (lane == 0) { sh_s[wid] = s; sh_ss[wid] = ss; }
    __syncthreads();
    s = 0.f; ss = 0.f;
#pragma unroll
    for (int w = 0; w < 8; w++) { s += sh_s[w]; ss += sh_ss[w]; }

    const float mu  = s * (1.0f / D_);
    const float var = ss * (1.0f / D_) - mu * mu;
    const float r   = rsqrtf(var + EPSLN);
#pragma unroll
    for (int t = 0; t < 3; t++) {
        int c = tid + t * 256;
        out[base + c] = (v[t] - mu) * r * g[c] + beta[c];
    }
}

// ---------------------------------------------------------------------------
extern "C" void kernel_launch(void* const* d_in, const int* in_sizes, int n_in,
                              void* d_out, int out_size)
{
    const float* x     = (const float*)d_in[0];
    const float* w_row = (const float*)d_in[1];
    const float* b_row = (const float*)d_in[2];
    const float* w_col = (const float*)d_in[3];
    const float* b_col = (const float*)d_in[4];
    const float* g1    = (const float*)d_in[5];
    const float* beta1 = (const float*)d_in[6];
    const float* g2    = (const float*)d_in[7];
    const float* beta2 = (const float*)d_in[8];
    const int*   pmask = (const int*)d_in[9];      // bool -> int32 in harness
    float* out = (float*)d_out;

    float *qkv, *tmp;
    cudaGetSymbolAddress((void**)&qkv, g_qkv);
    cudaGetSymbolAddress((void**)&tmp, g_tmp);

    const int smem_row = (256 * 65 + 2 * 256 * 64 + 256) * 4;   // ~195 KB
    const int smem_col = (128 * 65 + 2 * 128 * 64 + 128) * 4;   // ~97 KB
    cudaFuncSetAttribute(attn_row, cudaFuncAttributeMaxDynamicSharedMemorySize, smem_row);
    cudaFuncSetAttribute(attn_col, cudaFuncAttributeMaxDynamicSharedMemorySize, smem_col);

    dim3 gg(D3_ / 128, N_ / 128);   // (18, 256)

    // ---- row pass ----
    sgemm_nt_bias<<<gg, 256>>>(x, w_row, b_row, qkv, N_, D3_, D_);
    attn_row<<<dim3(H_, E_), 256, smem_row>>>(qkv, pmask, tmp);
    add_ln<<<N_, 256>>>(x, tmp, g1, beta1, out);

    // ---- column pass ----
    sgemm_nt_bias<<<gg, 256>>>(out, w_col, b_col, qkv, N_, D3_, D_);
    attn_col<<<dim3(H_, L_), 128, smem_col>>>(qkv, pmask, tmp);
    add_ln<<<N_, 256>>>(out, tmp, g2, beta2, out);
}

// round 6
// speedup vs baseline: 2.7955x; 2.7955x over previous
#include <cuda_runtime.h>
#include <cuda_bf16.h>
#include <cstdint>

// Fixed problem shapes
#define B_  1
#define E_  128
#define L_  256
#define H_  12
#define DH_ 64
#define D_  768          // H_*DH_
#define D3_ 2304         // 3*D_
#define N_  32768        // B_*E_*L_
#define EPSLN 1e-5f
#define NEGV  -10000.0f

// Scratch (allocations forbidden -> device globals)
__device__ float g_qkv[(size_t)N_ * D3_];            // 302 MB
__device__ float g_tmp[(size_t)N_ * D_];             // 100 MB
__device__ __nv_bfloat16 g_ah[(size_t)N_ * D_];      // 50 MB
__device__ __nv_bfloat16 g_al[(size_t)N_ * D_];      // 50 MB
__device__ __nv_bfloat16 g_wrh[(size_t)D3_ * D_];
__device__ __nv_bfloat16 g_wrl[(size_t)D3_ * D_];
__device__ __nv_bfloat16 g_wch[(size_t)D3_ * D_];
__device__ __nv_bfloat16 g_wcl[(size_t)D3_ * D_];

// ---------------------------------------------------------------------------
// arch-agnostic PTX helpers (mma.sync / ldmatrix / cp.async)
// ---------------------------------------------------------------------------
__device__ __forceinline__ uint32_t smem_u32(const void* p) {
    uint32_t a;
    asm("{ .reg .u64 t; cvta.to.shared.u64 t, %1; cvt.u32.u64 %0, t; }" : "=r"(a) : "l"(p));
    return a;
}
__device__ __forceinline__ void cp16(uint32_t s, const void* g) {
    asm volatile("cp.async.cg.shared.global [%0], [%1], 16;" :: "r"(s), "l"(g) : "memory");
}
__device__ __forceinline__ void cp_commit() {
    asm volatile("cp.async.commit_group;" ::: "memory");
}
template <int N>
__device__ __forceinline__ void cp_wait() {
    asm volatile("cp.async.wait_group %0;" :: "n"(N) : "memory");
}
__device__ __forceinline__ void ldsm4(uint32_t* r, uint32_t a) {
    asm volatile("ldmatrix.sync.aligned.m8n8.x4.shared.b16 {%0,%1,%2,%3}, [%4];"
                 : "=r"(r[0]), "=r"(r[1]), "=r"(r[2]), "=r"(r[3]) : "r"(a));
}
__device__ __forceinline__ void ldsm2(uint32_t* r, uint32_t a) {
    asm volatile("ldmatrix.sync.aligned.m8n8.x2.shared.b16 {%0,%1}, [%2];"
                 : "=r"(r[0]), "=r"(r[1]) : "r"(a));
}
__device__ __forceinline__ void mma16816(float* d, const uint32_t* a, const uint32_t* b) {
    asm volatile(
        "mma.sync.aligned.m16n8k16.row.col.f32.bf16.bf16.f32 "
        "{%0,%1,%2,%3}, {%4,%5,%6,%7}, {%8,%9}, {%0,%1,%2,%3};"
        : "+f"(d[0]), "+f"(d[1]), "+f"(d[2]), "+f"(d[3])
        : "r"(a[0]), "r"(a[1]), "r"(a[2]), "r"(a[3]), "r"(b[0]), "r"(b[1]));
}

// ---------------------------------------------------------------------------
// split: fp32 -> bf16 hi + bf16 lo
// ---------------------------------------------------------------------------
__global__ __launch_bounds__(256) void split_f32(
    const float* __restrict__ in, __nv_bfloat16* __restrict__ hi,
    __nv_bfloat16* __restrict__ lo, int n)
{
    int i = (blockIdx.x * 256 + threadIdx.x) * 4;
    if (i >= n) return;
    float4 v = *(const float4*)(in + i);
    float f[4] = {v.x, v.y, v.z, v.w};
    __nv_bfloat16 h[4], l[4];
#pragma unroll
    for (int q = 0; q < 4; q++) {
        h[q] = __float2bfloat16(f[q]);
        l[q] = __float2bfloat16(f[q] - __bfloat162float(h[q]));
    }
    *(__nv_bfloat162*)(hi + i)     = __halves2bfloat162(h[0], h[1]);
    *(__nv_bfloat162*)(hi + i + 2) = __halves2bfloat162(h[2], h[3]);
    *(__nv_bfloat162*)(lo + i)     = __halves2bfloat162(l[0], l[1]);
    *(__nv_bfloat162*)(lo + i + 2) = __halves2bfloat162(l[2], l[3]);
}

// ---------------------------------------------------------------------------
// bf16 3-way-split GEMM via mma.sync (HMMA):
//   C[n,m] = sum_k A[n,k]*B[m,k] + bias[m],  A=Ah+Al, B=Bh+Bl
//   C = Ah*Bh + Ah*Bl + Al*Bh (fp32 accum)
// CTA tile 128x128, BK=32 bf16, double-buffered cp.async, 8 warps (2x4),
// warp tile 64x32 (4x4 mma m16n8k16). grid = (2304/128, 32768/128).
// ---------------------------------------------------------------------------
#define GK 768
#define GM 2304
#define BKC 32
#define NIT 24                      // 768/32
#define STRD 40                     // smem row stride in bf16 (32 + 8 pad)
#define BUF_B (128 * STRD * 2)      // 10240 bytes per buffer
#define STAGE_B (4 * BUF_B)         // 40960 bytes (Ah,Al,Bh,Bl)
#define SMEM_GEMM (2 * STAGE_B)     // 81920 bytes

__device__ __forceinline__ void issue_stage(
    uint32_t smb, int stage, int kc,
    const __nv_bfloat16* __restrict__ pA0, const __nv_bfloat16* __restrict__ pA1,
    const __nv_bfloat16* __restrict__ pB0, const __nv_bfloat16* __restrict__ pB1,
    int tid)
{
    const __nv_bfloat16* src[4] = {pA0, pA1, pB0, pB1};
    const uint32_t sb = smb + (uint32_t)stage * STAGE_B;
    // per buffer: 128 rows x 32 cols = 512 x 16B chunks; 256 threads x 2
#pragma unroll
    for (int buf = 0; buf < 4; buf++) {
#pragma unroll
        for (int i = 0; i < 2; i++) {
            int idx = i * 256 + tid;          // 0..511
            int r = idx >> 2, c16 = idx & 3;  // row, 16B-chunk in row
            const void* g = src[buf] + (size_t)r * GK + kc + c16 * 8;
            uint32_t s = sb + (uint32_t)buf * BUF_B + (uint32_t)(r * STRD + c16 * 8) * 2;
            cp16(s, g);
        }
    }
    cp_commit();
}

__global__ __launch_bounds__(256, 1) void gemm_hmma_x3(
    const __nv_bfloat16* __restrict__ Ah, const __nv_bfloat16* __restrict__ Al,
    const __nv_bfloat16* __restrict__ Bh, const __nv_bfloat16* __restrict__ Bl,
    const float* __restrict__ bias, float* __restrict__ C)
{
    extern __shared__ char dynsm[];
    const uint32_t smb = smem_u32(dynsm);

    const int tid  = threadIdx.x;
    const int wid  = tid >> 5, lane = tid & 31;
    const int wm   = wid >> 2;        // 0..1  (64-row slab)
    const int wn   = wid & 3;         // 0..3  (32-col slab)
    const int tileN = blockIdx.x;     // 0..17
    const int tileM = blockIdx.y;     // 0..255

    const __nv_bfloat16* pA0 = Ah + (size_t)tileM * 128 * GK;
    const __nv_bfloat16* pA1 = Al + (size_t)tileM * 128 * GK;
    const __nv_bfloat16* pB0 = Bh + (size_t)tileN * 128 * GK;
    const __nv_bfloat16* pB1 = Bl + (size_t)tileN * 128 * GK;

    // prologue: stages 0,1
    issue_stage(smb, 0, 0,   pA0, pA1, pB0, pB1, tid);
    issue_stage(smb, 1, BKC, pA0, pA1, pB0, pB1, tid);

    float acc[4][4][4];
#pragma unroll
    for (int a = 0; a < 4; a++)
#pragma unroll
        for (int b = 0; b < 4; b++)
#pragma unroll
            for (int c = 0; c < 4; c++) acc[a][b][c] = 0.f;

    // per-lane ldmatrix address components (bytes)
    const int aRow = (lane & 15);             // 0..15
    const int aColB = (lane >> 4) * 16;       // 0 / 16  (k +0/+8 elems)
    const int bRow = (lane & 7);
    const int bColB = ((lane >> 3) & 1) * 16;

    for (int it = 0; it < NIT; it++) {
        if (it < NIT - 2) cp_wait<1>(); else cp_wait<0>();
        __syncthreads();

        const uint32_t sb = smb + (uint32_t)(it & 1) * STAGE_B;
        const uint32_t sAh = sb;
        const uint32_t sAl = sb + BUF_B;
        const uint32_t sBh = sb + 2 * BUF_B;
        const uint32_t sBl = sb + 3 * BUF_B;

#pragma unroll
        for (int ks = 0; ks < 2; ks++) {
            const int kb = ks * 32;   // byte offset of k-step (16 elems)
            uint32_t ah[4][4], al4[4][4], bh[4][2], bl[4][2];
#pragma unroll
            for (int mt = 0; mt < 4; mt++) {
                uint32_t off = (uint32_t)((wm * 64 + mt * 16 + aRow) * (STRD * 2) + kb + aColB);
                ldsm4(ah[mt],  sAh + off);
                ldsm4(al4[mt], sAl + off);
            }
#pragma unroll
            for (int nt = 0; nt < 4; nt++) {
                uint32_t off = (uint32_t)((wn * 32 + nt * 8 + bRow) * (STRD * 2) + kb + bColB);
                ldsm2(bh[nt], sBh + off);
                ldsm2(bl[nt], sBl + off);
            }
#pragma unroll
            for (int mt = 0; mt < 4; mt++)
#pragma unroll
                for (int nt = 0; nt < 4; nt++) {
                    mma16816(acc[mt][nt], ah[mt],  bh[nt]);
                    mma16816(acc[mt][nt], ah[mt],  bl[nt]);
                    mma16816(acc[mt][nt], al4[mt], bh[nt]);
                }
        }
        __syncthreads();
        if (it + 2 < NIT)
            issue_stage(smb, it & 1, (it + 2) * BKC, pA0, pA1, pB0, pB1, tid);
    }

    // epilogue: D frag m16n8 mapping -> gmem + bias
    const int r0 = tileM * 128 + wm * 64 + (lane >> 2);
    const int c0 = tileN * 128 + wn * 32 + (lane & 3) * 2;
#pragma unroll
    for (int mt = 0; mt < 4; mt++) {
#pragma unroll
        for (int nt = 0; nt < 4; nt++) {
            const int row = r0 + mt * 16;
            const int col = c0 + nt * 8;
            const float b0 = bias[col], b1 = bias[col + 1];
            float2 v0 = {acc[mt][nt][0] + b0, acc[mt][nt][1] + b1};
            float2 v1 = {acc[mt][nt][2] + b0, acc[mt][nt][3] + b1};
            *(float2*)(C + (size_t)row * GM + col)       = v0;
            *(float2*)(C + (size_t)(row + 8) * GM + col) = v1;
        }
    }
}

// ---------------------------------------------------------------------------
// Row attention: for each (e,h), attend over L=256 keys.
// ---------------------------------------------------------------------------
__global__ __launch_bounds__(256, 1) void attn_row(
    const float* __restrict__ qkv, const int* __restrict__ mask,
    float* __restrict__ out)
{
    extern __shared__ float sm[];
    float* Qs   = sm;                   // 256*65
    float* Ks   = Qs + 256 * 65;        // 256*64
    float* Vs   = Ks + 256 * 64;        // 256*64
    float* negs = Vs + 256 * 64;        // 256

    const int h = blockIdx.x, e = blockIdx.y;
    const int tid = threadIdx.x;
    const size_t baseQ = (size_t)e * 256 * D3_ + h * 64;

    for (int idx = tid; idx < 256 * 64; idx += 256) {
        int j = idx >> 6, d = idx & 63;
        size_t rb = baseQ + (size_t)j * D3_ + d;
        Qs[j * 65 + d] = qkv[rb] * 0.125f;
        Ks[idx]        = qkv[rb + 768];
        Vs[idx]        = qkv[rb + 1536];
    }
    if (tid < 256) negs[tid] = mask[e * 256 + tid] ? NEGV : 0.f;
    __syncthreads();

    const int i = tid;
    float q[64];
#pragma unroll
    for (int d = 0; d < 64; d++) q[d] = Qs[i * 65 + d];

    float m = -1e30f, l = 0.f, acc[64];
#pragma unroll
    for (int d = 0; d < 64; d++) acc[d] = 0.f;

    for (int j = 0; j < 256; j++) {
        const float* kj = Ks + j * 64;
        float s = 0.f;
#pragma unroll
        for (int d = 0; d < 64; d++) s += q[d] * kj[d];
        s += negs[j];
        const float* vj = Vs + j * 64;
        if (s <= m) {
            float p = __expf(s - m);
            l += p;
#pragma unroll
            for (int d = 0; d < 64; d++) acc[d] += p * vj[d];
        } else {
            float corr = __expf(m - s);
            m = s;
            l = l * corr + 1.f;
#pragma unroll
            for (int d = 0; d < 64; d++) acc[d] = acc[d] * corr + vj[d];
        }
    }
    const float inv = 1.f / l;
    const size_t ob = ((size_t)e * 256 + i) * D_ + h * 64;
#pragma unroll
    for (int d = 0; d < 64; d++) out[ob + d] = acc[d] * inv;
}

// ---------------------------------------------------------------------------
// Column attention: for each (l,h), attend over E=128 keys.
// ---------------------------------------------------------------------------
__global__ __launch_bounds__(128, 1) void attn_col(
    const float* __restrict__ qkv, const int* __restrict__ mask,
    float* __restrict__ out)
{
    extern __shared__ float sm[];
    float* Qs   = sm;                   // 128*65
    float* Ks   = Qs + 128 * 65;        // 128*64
    float* Vs   = Ks + 128 * 64;        // 128*64
    float* negs = Vs + 128 * 64;        // 128

    const int h = blockIdx.x, l = blockIdx.y;
    const int tid = threadIdx.x;

    for (int idx = tid; idx < 128 * 64; idx += 128) {
        int j = idx >> 6, d = idx & 63;
        size_t rb = ((size_t)j * 256 + l) * D3_ + h * 64 + d;
        Qs[j * 65 + d] = qkv[rb] * 0.125f;
        Ks[idx]        = qkv[rb + 768];
        Vs[idx]        = qkv[rb + 1536];
    }
    if (tid < 128) negs[tid] = mask[tid * 256 + l] ? NEGV : 0.f;
    __syncthreads();

    const int i = tid;
    float q[64];
#pragma unroll
    for (int d = 0; d < 64; d++) q[d] = Qs[i * 65 + d];

    float m = -1e30f, lsum = 0.f, acc[64];
#pragma unroll
    for (int d = 0; d < 64; d++) acc[d] = 0.f;

    for (int j = 0; j < 128; j++) {
        const float* kj = Ks + j * 64;
        float s = 0.f;
#pragma unroll
        for (int d = 0; d < 64; d++) s += q[d] * kj[d];
        s += negs[j];
        const float* vj = Vs + j * 64;
        if (s <= m) {
            float p = __expf(s - m);
            lsum += p;
#pragma unroll
            for (int d = 0; d < 64; d++) acc[d] += p * vj[d];
        } else {
            float corr = __expf(m - s);
            m = s;
            lsum = lsum * corr + 1.f;
#pragma unroll
            for (int d = 0; d < 64; d++) acc[d] = acc[d] * corr + vj[d];
        }
    }
    const float inv = 1.f / lsum;
    const size_t ob = ((size_t)i * 256 + l) * D_ + h * 64;
#pragma unroll
    for (int d = 0; d < 64; d++) out[ob + d] = acc[d] * inv;
}

// ---------------------------------------------------------------------------
// out = LayerNorm(a + b) * g + beta
// ---------------------------------------------------------------------------
__global__ __launch_bounds__(256) void add_ln(
    const float* __restrict__ a, const float* __restrict__ b,
    const float* __restrict__ g, const float* __restrict__ beta,
    float* __restrict__ out)
{
    const int n = blockIdx.x, tid = threadIdx.x;
    const size_t base = (size_t)n * D_;

    float v[3], s = 0.f, ss = 0.f;
#pragma unroll
    for (int t = 0; t < 3; t++) {
        int c = tid + t * 256;
        float x = a[base + c] + b[base + c];
        v[t] = x; s += x; ss += x * x;
    }
#pragma unroll
    for (int off = 16; off > 0; off >>= 1) {
        s  += __shfl_xor_sync(0xffffffffu, s,  off);
        ss += __shfl_xor_sync(0xffffffffu, ss, off);
    }
    __shared__ float sh_s[8], sh_ss[8];
    const int wid = tid >> 5, lane = tid & 31;
    if (lane == 0) { sh_s[wid] = s; sh_ss[wid] = ss; }
    __syncthreads();
    s = 0.f; ss = 0.f;
#pragma unroll
    for (int w = 0; w < 8; w++) { s += sh_s[w]; ss += sh_ss[w]; }

    const float mu  = s * (1.0f / D_);
    const float var = ss * (1.0f / D_) - mu * mu;
    const float r   = rsqrtf(var + EPSLN);
#pragma unroll
    for (int t = 0; t < 3; t++) {
        int c = tid + t * 256;
        out[base + c] = (v[t] - mu) * r * g[c] + beta[c];
    }
}

// ---------------------------------------------------------------------------
extern "C" void kernel_launch(void* const* d_in, const int* in_sizes, int n_in,
                              void* d_out, int out_size)
{
    const float* x     = (const float*)d_in[0];
    const float* w_row = (const float*)d_in[1];
    const float* b_row = (const float*)d_in[2];
    const float* w_col = (const float*)d_in[3];
    const float* b_col = (const float*)d_in[4];
    const float* g1    = (const float*)d_in[5];
    const float* beta1 = (const float*)d_in[6];
    const float* g2    = (const float*)d_in[7];
    const float* beta2 = (const float*)d_in[8];
    const int*   pmask = (const int*)d_in[9];
    float* out = (float*)d_out;

    float *qkv, *tmp;
    cudaGetSymbolAddress((void**)&qkv, g_qkv);
    cudaGetSymbolAddress((void**)&tmp, g_tmp);
    __nv_bfloat16 *ah, *al, *wrh, *wrl, *wch, *wcl;
    cudaGetSymbolAddress((void**)&ah,  g_ah);
    cudaGetSymbolAddress((void**)&al,  g_al);
    cudaGetSymbolAddress((void**)&wrh, g_wrh);
    cudaGetSymbolAddress((void**)&wrl, g_wrl);
    cudaGetSymbolAddress((void**)&wch, g_wch);
    cudaGetSymbolAddress((void**)&wcl, g_wcl);

    const int smem_row = (256 * 65 + 2 * 256 * 64 + 256) * 4;
    const int smem_col = (128 * 65 + 2 * 128 * 64 + 128) * 4;
    cudaFuncSetAttribute(attn_row, cudaFuncAttributeMaxDynamicSharedMemorySize, smem_row);
    cudaFuncSetAttribute(attn_col, cudaFuncAttributeMaxDynamicSharedMemorySize, smem_col);
    cudaFuncSetAttribute(gemm_hmma_x3, cudaFuncAttributeMaxDynamicSharedMemorySize, SMEM_GEMM);

    const int nx = N_ * D_;       // 25165824
    const int nw = D3_ * D_;      // 1769472
    dim3 gemm_grid(GM / 128, N_ / 128);   // (18, 256)

    // splits
    split_f32<<<nw / 1024, 256>>>(w_row, wrh, wrl, nw);
    split_f32<<<nw / 1024, 256>>>(w_col, wch, wcl, nw);
    split_f32<<<nx / 1024, 256>>>(x, ah, al, nx);

    // ---- row pass ----
    gemm_hmma_x3<<<gemm_grid, 256, SMEM_GEMM>>>(ah, al, wrh, wrl, b_row, qkv);
    attn_row<<<dim3(H_, E_), 256, smem_row>>>(qkv, pmask, tmp);
    add_ln<<<N_, 256>>>(x, tmp, g1, beta1, out);

    // ---- column pass ----
    split_f32<<<nx / 1024, 256>>>(out, ah, al, nx);
    gemm_hmma_x3<<<gemm_grid, 256, SMEM_GEMM>>>(ah, al, wch, wcl, b_col, qkv);
    attn_col<<<dim3(H_, L_), 128, smem_col>>>(qkv, pmask, tmp);
    add_ln<<<N_, 256>>>(out, tmp, g2, beta2, out);
}

// round 7
// speedup vs baseline: 4.0722x; 1.4567x over previous
#include <cuda_runtime.h>
#include <cuda_bf16.h>
#include <cstdint>

// Fixed problem shapes
#define B_  1
#define E_  128
#define L_  256
#define H_  12
#define DH_ 64
#define D_  768          // H_*DH_
#define D3_ 2304         // 3*D_
#define N_  32768        // B_*E_*L_
#define EPSLN 1e-5f
#define NEGV  -10000.0f

// Scratch (allocations forbidden -> device globals)
__device__ float g_qkv[(size_t)N_ * D3_];            // 302 MB
__device__ float g_tmp[(size_t)N_ * D_];             // 100 MB
__device__ __nv_bfloat16 g_ah[(size_t)N_ * D_];      // 50 MB
__device__ __nv_bfloat16 g_al[(size_t)N_ * D_];      // 50 MB
__device__ __nv_bfloat16 g_wrh[(size_t)D3_ * D_];
__device__ __nv_bfloat16 g_wrl[(size_t)D3_ * D_];
__device__ __nv_bfloat16 g_wch[(size_t)D3_ * D_];
__device__ __nv_bfloat16 g_wcl[(size_t)D3_ * D_];

// ---------------------------------------------------------------------------
// arch-agnostic PTX helpers (mma.sync / ldmatrix / cp.async)
// ---------------------------------------------------------------------------
__device__ __forceinline__ uint32_t smem_u32(const void* p) {
    uint32_t a;
    asm("{ .reg .u64 t; cvta.to.shared.u64 t, %1; cvt.u32.u64 %0, t; }" : "=r"(a) : "l"(p));
    return a;
}
__device__ __forceinline__ void cp16(uint32_t s, const void* g) {
    asm volatile("cp.async.cg.shared.global [%0], [%1], 16;" :: "r"(s), "l"(g) : "memory");
}
__device__ __forceinline__ void cp_commit() {
    asm volatile("cp.async.commit_group;" ::: "memory");
}
template <int N>
__device__ __forceinline__ void cp_wait() {
    asm volatile("cp.async.wait_group %0;" :: "n"(N) : "memory");
}
__device__ __forceinline__ void ldsm4(uint32_t* r, uint32_t a) {
    asm volatile("ldmatrix.sync.aligned.m8n8.x4.shared.b16 {%0,%1,%2,%3}, [%4];"
                 : "=r"(r[0]), "=r"(r[1]), "=r"(r[2]), "=r"(r[3]) : "r"(a));
}
__device__ __forceinline__ void ldsm2(uint32_t* r, uint32_t a) {
    asm volatile("ldmatrix.sync.aligned.m8n8.x2.shared.b16 {%0,%1}, [%2];"
                 : "=r"(r[0]), "=r"(r[1]) : "r"(a));
}
__device__ __forceinline__ void ldsm2t(uint32_t* r, uint32_t a) {
    asm volatile("ldmatrix.sync.aligned.m8n8.x2.trans.shared.b16 {%0,%1}, [%2];"
                 : "=r"(r[0]), "=r"(r[1]) : "r"(a));
}
__device__ __forceinline__ void mma16816(float* d, const uint32_t* a, const uint32_t* b) {
    asm volatile(
        "mma.sync.aligned.m16n8k16.row.col.f32.bf16.bf16.f32 "
        "{%0,%1,%2,%3}, {%4,%5,%6,%7}, {%8,%9}, {%0,%1,%2,%3};"
        : "+f"(d[0]), "+f"(d[1]), "+f"(d[2]), "+f"(d[3])
        : "r"(a[0]), "r"(a[1]), "r"(a[2]), "r"(a[3]), "r"(b[0]), "r"(b[1]));
}
__device__ __forceinline__ uint32_t pack2(__nv_bfloat16 a, __nv_bfloat16 b) {
    __nv_bfloat162 t = __halves2bfloat162(a, b);
    return *reinterpret_cast<uint32_t*>(&t);
}

// ---------------------------------------------------------------------------
// split: fp32 -> bf16 hi + bf16 lo
// ---------------------------------------------------------------------------
__global__ __launch_bounds__(256) void split_f32(
    const float* __restrict__ in, __nv_bfloat16* __restrict__ hi,
    __nv_bfloat16* __restrict__ lo, int n)
{
    int i = (blockIdx.x * 256 + threadIdx.x) * 4;
    if (i >= n) return;
    float4 v = *(const float4*)(in + i);
    float f[4] = {v.x, v.y, v.z, v.w};
    __nv_bfloat16 h[4], l[4];
#pragma unroll
    for (int q = 0; q < 4; q++) {
        h[q] = __float2bfloat16(f[q]);
        l[q] = __float2bfloat16(f[q] - __bfloat162float(h[q]));
    }
    *(__nv_bfloat162*)(hi + i)     = __halves2bfloat162(h[0], h[1]);
    *(__nv_bfloat162*)(hi + i + 2) = __halves2bfloat162(h[2], h[3]);
    *(__nv_bfloat162*)(lo + i)     = __halves2bfloat162(l[0], l[1]);
    *(__nv_bfloat162*)(lo + i + 2) = __halves2bfloat162(l[2], l[3]);
}

// ---------------------------------------------------------------------------
// bf16 3-way-split GEMM via mma.sync (HMMA) — unchanged from R5 (passing)
// ---------------------------------------------------------------------------
#define GK 768
#define GM 2304
#define BKC 32
#define NIT 24
#define STRD 40
#define BUF_B (128 * STRD * 2)
#define STAGE_B (4 * BUF_B)
#define SMEM_GEMM (2 * STAGE_B)

__device__ __forceinline__ void issue_stage(
    uint32_t smb, int stage, int kc,
    const __nv_bfloat16* __restrict__ pA0, const __nv_bfloat16* __restrict__ pA1,
    const __nv_bfloat16* __restrict__ pB0, const __nv_bfloat16* __restrict__ pB1,
    int tid)
{
    const __nv_bfloat16* src[4] = {pA0, pA1, pB0, pB1};
    const uint32_t sb = smb + (uint32_t)stage * STAGE_B;
#pragma unroll
    for (int buf = 0; buf < 4; buf++) {
#pragma unroll
        for (int i = 0; i < 2; i++) {
            int idx = i * 256 + tid;
            int r = idx >> 2, c16 = idx & 3;
            const void* g = src[buf] + (size_t)r * GK + kc + c16 * 8;
            uint32_t s = sb + (uint32_t)buf * BUF_B + (uint32_t)(r * STRD + c16 * 8) * 2;
            cp16(s, g);
        }
    }
    cp_commit();
}

__global__ __launch_bounds__(256, 1) void gemm_hmma_x3(
    const __nv_bfloat16* __restrict__ Ah, const __nv_bfloat16* __restrict__ Al,
    const __nv_bfloat16* __restrict__ Bh, const __nv_bfloat16* __restrict__ Bl,
    const float* __restrict__ bias, float* __restrict__ C)
{
    extern __shared__ char dynsm[];
    const uint32_t smb = smem_u32(dynsm);

    const int tid  = threadIdx.x;
    const int wid  = tid >> 5, lane = tid & 31;
    const int wm   = wid >> 2;
    const int wn   = wid & 3;
    const int tileN = blockIdx.x;
    const int tileM = blockIdx.y;

    const __nv_bfloat16* pA0 = Ah + (size_t)tileM * 128 * GK;
    const __nv_bfloat16* pA1 = Al + (size_t)tileM * 128 * GK;
    const __nv_bfloat16* pB0 = Bh + (size_t)tileN * 128 * GK;
    const __nv_bfloat16* pB1 = Bl + (size_t)tileN * 128 * GK;

    issue_stage(smb, 0, 0,   pA0, pA1, pB0, pB1, tid);
    issue_stage(smb, 1, BKC, pA0, pA1, pB0, pB1, tid);

    float acc[4][4][4];
#pragma unroll
    for (int a = 0; a < 4; a++)
#pragma unroll
        for (int b = 0; b < 4; b++)
#pragma unroll
            for (int c = 0; c < 4; c++) acc[a][b][c] = 0.f;

    const int aRow = (lane & 15);
    const int aColB = (lane >> 4) * 16;
    const int bRow = (lane & 7);
    const int bColB = ((lane >> 3) & 1) * 16;

    for (int it = 0; it < NIT; it++) {
        if (it < NIT - 2) cp_wait<1>(); else cp_wait<0>();
        __syncthreads();

        const uint32_t sb = smb + (uint32_t)(it & 1) * STAGE_B;
        const uint32_t sAh = sb;
        const uint32_t sAl = sb + BUF_B;
        const uint32_t sBh = sb + 2 * BUF_B;
        const uint32_t sBl = sb + 3 * BUF_B;

#pragma unroll
        for (int ks = 0; ks < 2; ks++) {
            const int kb = ks * 32;
            uint32_t ah[4][4], al4[4][4], bh[4][2], bl[4][2];
#pragma unroll
            for (int mt = 0; mt < 4; mt++) {
                uint32_t off = (uint32_t)((wm * 64 + mt * 16 + aRow) * (STRD * 2) + kb + aColB);
                ldsm4(ah[mt],  sAh + off);
                ldsm4(al4[mt], sAl + off);
            }
#pragma unroll
            for (int nt = 0; nt < 4; nt++) {
                uint32_t off = (uint32_t)((wn * 32 + nt * 8 + bRow) * (STRD * 2) + kb + bColB);
                ldsm2(bh[nt], sBh + off);
                ldsm2(bl[nt], sBl + off);
            }
#pragma unroll
            for (int mt = 0; mt < 4; mt++)
#pragma unroll
                for (int nt = 0; nt < 4; nt++) {
                    mma16816(acc[mt][nt], ah[mt],  bh[nt]);
                    mma16816(acc[mt][nt], ah[mt],  bl[nt]);
                    mma16816(acc[mt][nt], al4[mt], bh[nt]);
                }
        }
        __syncthreads();
        if (it + 2 < NIT)
            issue_stage(smb, it & 1, (it + 2) * BKC, pA0, pA1, pB0, pB1, tid);
    }

    const int r0 = tileM * 128 + wm * 64 + (lane >> 2);
    const int c0 = tileN * 128 + wn * 32 + (lane & 3) * 2;
#pragma unroll
    for (int mt = 0; mt < 4; mt++) {
#pragma unroll
        for (int nt = 0; nt < 4; nt++) {
            const int row = r0 + mt * 16;
            const int col = c0 + nt * 8;
            const float b0 = bias[col], b1 = bias[col + 1];
            float2 v0 = {acc[mt][nt][0] + b0, acc[mt][nt][1] + b1};
            float2 v1 = {acc[mt][nt][2] + b0, acc[mt][nt][3] + b1};
            *(float2*)(C + (size_t)row * GM + col)       = v0;
            *(float2*)(C + (size_t)(row + 8) * GM + col) = v1;
        }
    }
}

// ---------------------------------------------------------------------------
// Flash-style HMMA attention (bf16 3-way split for both QK and PV).
// Template MT: m-tiles per warp. NQ = MT*128 queries = keys per (slice, head).
//   row pass: MT=2, grid (12, 128), base = e*256, step = 1
//   col pass: MT=1, grid (12, 256), base = l,     step = 256
// 8 warps, warp owns MT*16 query rows; keys processed in chunks of 64.
// ---------------------------------------------------------------------------
#define ASTR 72                       // smem row stride in bf16 (64 + 8 pad)
#define ASTRB 144                     // bytes

template <int MT>
__global__ __launch_bounds__(256, 1) void attn_mma(
    const float* __restrict__ qkv, const int* __restrict__ mask,
    float* __restrict__ out, int colmode)
{
    constexpr int NQ  = MT * 128;
    constexpr int NCH = MT * 2;       // key chunks of 64
    extern __shared__ __align__(16) char smraw[];
    __nv_bfloat16* sQh = (__nv_bfloat16*)smraw;
    __nv_bfloat16* sQl = sQh + NQ * ASTR;
    __nv_bfloat16* sKh = sQl + NQ * ASTR;
    __nv_bfloat16* sKl = sKh + 64 * ASTR;
    __nv_bfloat16* sVh = sKl + 64 * ASTR;
    __nv_bfloat16* sVl = sVh + 64 * ASTR;
    float*        negs = (float*)(sVl + 64 * ASTR);

    const int tid  = threadIdx.x;
    const int wid  = tid >> 5, lane = tid & 31;
    const int h    = blockIdx.x;
    const int base = colmode ? (int)blockIdx.y : (int)blockIdx.y * 256;
    const int step = colmode ? 256 : 1;

    const uint32_t uQh = smem_u32(sQh), uQl = smem_u32(sQl);
    const uint32_t uKh = smem_u32(sKh), uKl = smem_u32(sKl);
    const uint32_t uVh = smem_u32(sVh);
    const uint32_t VLOFF = 64 * ASTRB;   // sVl - sVh

    // ---- load Q (scaled by DH^-0.5) + mask ----
    for (int i4 = tid; i4 < NQ * 16; i4 += 256) {
        int r = i4 >> 4, c4 = (i4 & 15) * 4;
        const float* src = qkv + (size_t)(base + r * step) * D3_ + h * 64 + c4;
        float4 v = *(const float4*)src;
        float f[4] = {v.x * 0.125f, v.y * 0.125f, v.z * 0.125f, v.w * 0.125f};
        __nv_bfloat16 hh[4], ll[4];
#pragma unroll
        for (int q = 0; q < 4; q++) {
            hh[q] = __float2bfloat16(f[q]);
            ll[q] = __float2bfloat16(f[q] - __bfloat162float(hh[q]));
        }
        __nv_bfloat162* dh = (__nv_bfloat162*)(sQh + r * ASTR + c4);
        __nv_bfloat162* dl = (__nv_bfloat162*)(sQl + r * ASTR + c4);
        dh[0] = __halves2bfloat162(hh[0], hh[1]); dh[1] = __halves2bfloat162(hh[2], hh[3]);
        dl[0] = __halves2bfloat162(ll[0], ll[1]); dl[1] = __halves2bfloat162(ll[2], ll[3]);
    }
    for (int i = tid; i < NQ; i += 256)
        negs[i] = mask[base + i * step] ? NEGV : 0.f;

    float s[MT][8][4], o[MT][8][4], mrow[MT][2], lrow[MT][2];
#pragma unroll
    for (int mt = 0; mt < MT; mt++) {
        mrow[mt][0] = mrow[mt][1] = -1e30f;
        lrow[mt][0] = lrow[mt][1] = 0.f;
#pragma unroll
        for (int nt = 0; nt < 8; nt++)
#pragma unroll
            for (int c = 0; c < 4; c++) o[mt][nt][c] = 0.f;
    }

    const int aRow  = lane & 15;
    const int aColB = (lane >> 4) * 16;
    const int bRow  = lane & 7;
    const int bColB = ((lane >> 3) & 1) * 16;

    for (int ch = 0; ch < NCH; ch++) {
        // ---- gather K/V chunk (64 keys) into regs ----
        float4 kreg[4], vreg[4];
#pragma unroll
        for (int it = 0; it < 4; it++) {
            int i4 = it * 256 + tid;
            int r = i4 >> 4, c4 = (i4 & 15) * 4;
            const float* src = qkv + (size_t)(base + (ch * 64 + r) * step) * D3_ + h * 64 + c4;
            kreg[it] = *(const float4*)(src + 768);
            vreg[it] = *(const float4*)(src + 1536);
        }
        __syncthreads();   // previous chunk's compute done with K/V smem
#pragma unroll
        for (int it = 0; it < 4; it++) {
            int i4 = it * 256 + tid;
            int r = i4 >> 4, c4 = (i4 & 15) * 4;
            float fk[4] = {kreg[it].x, kreg[it].y, kreg[it].z, kreg[it].w};
            float fv[4] = {vreg[it].x, vreg[it].y, vreg[it].z, vreg[it].w};
            __nv_bfloat16 kh[4], kl[4], vh[4], vl[4];
#pragma unroll
            for (int q = 0; q < 4; q++) {
                kh[q] = __float2bfloat16(fk[q]);
                kl[q] = __float2bfloat16(fk[q] - __bfloat162float(kh[q]));
                vh[q] = __float2bfloat16(fv[q]);
                vl[q] = __float2bfloat16(fv[q] - __bfloat162float(vh[q]));
            }
            __nv_bfloat162* dkh = (__nv_bfloat162*)(sKh + r * ASTR + c4);
            __nv_bfloat162* dkl = (__nv_bfloat162*)(sKl + r * ASTR + c4);
            __nv_bfloat162* dvh = (__nv_bfloat162*)(sVh + r * ASTR + c4);
            __nv_bfloat162* dvl = (__nv_bfloat162*)(sVl + r * ASTR + c4);
            dkh[0] = __halves2bfloat162(kh[0], kh[1]); dkh[1] = __halves2bfloat162(kh[2], kh[3]);
            dkl[0] = __halves2bfloat162(kl[0], kl[1]); dkl[1] = __halves2bfloat162(kl[2], kl[3]);
            dvh[0] = __halves2bfloat162(vh[0], vh[1]); dvh[1] = __halves2bfloat162(vh[2], vh[3]);
            dvl[0] = __halves2bfloat162(vl[0], vl[1]); dvl[1] = __halves2bfloat162(vl[2], vl[3]);
        }
        __syncthreads();

        // ---- S = Q K^T (3-split), K-dim = 64 = 4 k16 steps ----
#pragma unroll
        for (int mt = 0; mt < MT; mt++)
#pragma unroll
            for (int nt = 0; nt < 8; nt++)
#pragma unroll
                for (int c = 0; c < 4; c++) s[mt][nt][c] = 0.f;

#pragma unroll
        for (int kq = 0; kq < 4; kq++) {
            uint32_t ah[MT][4], al[MT][4];
#pragma unroll
            for (int mt = 0; mt < MT; mt++) {
                uint32_t off = (uint32_t)((wid * (MT * 16) + mt * 16 + aRow) * ASTRB
                                          + kq * 32 + aColB);
                ldsm4(ah[mt], uQh + off);
                ldsm4(al[mt], uQl + off);
            }
#pragma unroll
            for (int nt = 0; nt < 8; nt++) {
                uint32_t kbh[2], kbl[2];
                uint32_t off = (uint32_t)((nt * 8 + bRow) * ASTRB + kq * 32 + bColB);
                ldsm2(kbh, uKh + off);
                ldsm2(kbl, uKl + off);
#pragma unroll
                for (int mt = 0; mt < MT; mt++) {
                    mma16816(s[mt][nt], ah[mt], kbh);
                    mma16816(s[mt][nt], ah[mt], kbl);
                    mma16816(s[mt][nt], al[mt], kbh);
                }
            }
        }

        // ---- mask + online softmax ----
#pragma unroll
        for (int nt = 0; nt < 8; nt++) {
            int j = ch * 64 + nt * 8 + (lane & 3) * 2;
            float n0 = negs[j], n1 = negs[j + 1];
#pragma unroll
            for (int mt = 0; mt < MT; mt++) {
                s[mt][nt][0] += n0; s[mt][nt][1] += n1;
                s[mt][nt][2] += n0; s[mt][nt][3] += n1;
            }
        }
#pragma unroll
        for (int mt = 0; mt < MT; mt++) {
#pragma unroll
            for (int hf = 0; hf < 2; hf++) {
                float rm = -1e30f;
#pragma unroll
                for (int nt = 0; nt < 8; nt++)
                    rm = fmaxf(rm, fmaxf(s[mt][nt][2 * hf], s[mt][nt][2 * hf + 1]));
                rm = fmaxf(rm, __shfl_xor_sync(0xffffffffu, rm, 1));
                rm = fmaxf(rm, __shfl_xor_sync(0xffffffffu, rm, 2));
                float mo = mrow[mt][hf];
                float mn = fmaxf(mo, rm);
                float corr = __expf(mo - mn);
                float rs = 0.f;
#pragma unroll
                for (int nt = 0; nt < 8; nt++) {
                    float p0 = __expf(s[mt][nt][2 * hf]     - mn);
                    float p1 = __expf(s[mt][nt][2 * hf + 1] - mn);
                    s[mt][nt][2 * hf] = p0; s[mt][nt][2 * hf + 1] = p1;
                    rs += p0 + p1;
                    o[mt][nt][2 * hf] *= corr; o[mt][nt][2 * hf + 1] *= corr;
                }
                rs += __shfl_xor_sync(0xffffffffu, rs, 1);
                rs += __shfl_xor_sync(0xffffffffu, rs, 2);
                lrow[mt][hf] = lrow[mt][hf] * corr + rs;
                mrow[mt][hf] = mn;
            }
        }

        // ---- O += P V (P in regs as A-frags, split; V via ldsm trans) ----
#pragma unroll
        for (int kk = 0; kk < 4; kk++) {
            uint32_t pah[MT][4], pal[MT][4];
#pragma unroll
            for (int mt = 0; mt < MT; mt++) {
#pragma unroll
                for (int q = 0; q < 4; q++) {
                    int nt = kk * 2 + (q >> 1);
                    int i0 = (q & 1) * 2;
                    float p0 = s[mt][nt][i0], p1 = s[mt][nt][i0 + 1];
                    __nv_bfloat16 h0 = __float2bfloat16(p0);
                    __nv_bfloat16 h1 = __float2bfloat16(p1);
                    pah[mt][q] = pack2(h0, h1);
                    __nv_bfloat16 l0 = __float2bfloat16(p0 - __bfloat162float(h0));
                    __nv_bfloat16 l1 = __float2bfloat16(p1 - __bfloat162float(h1));
                    pal[mt][q] = pack2(l0, l1);
                }
            }
#pragma unroll
            for (int nt = 0; nt < 8; nt++) {
                uint32_t vbh[2], vbl[2];
                uint32_t va = uVh + (uint32_t)((kk * 16 + (lane & 15)) * ASTRB + nt * 16);
                ldsm2t(vbh, va);
                ldsm2t(vbl, va + VLOFF);
#pragma unroll
                for (int mt = 0; mt < MT; mt++) {
                    mma16816(o[mt][nt], pah[mt], vbh);
                    mma16816(o[mt][nt], pah[mt], vbl);
                    mma16816(o[mt][nt], pal[mt], vbh);
                }
            }
        }
    }

    // ---- epilogue ----
#pragma unroll
    for (int mt = 0; mt < MT; mt++) {
#pragma unroll
        for (int hf = 0; hf < 2; hf++) {
            float inv = 1.f / lrow[mt][hf];
            int qrow = wid * (MT * 16) + mt * 16 + hf * 8 + (lane >> 2);
            size_t ob = (size_t)(base + qrow * step) * D_ + h * 64 + (lane & 3) * 2;
#pragma unroll
            for (int nt = 0; nt < 8; nt++) {
                float2 v = {o[mt][nt][2 * hf] * inv, o[mt][nt][2 * hf + 1] * inv};
                *(float2*)(out + ob + nt * 8) = v;
            }
        }
    }
}

#define SMEM_ATT_ROW ((2 * 256 * ASTR + 4 * 64 * ASTR) * 2 + 256 * 4)   // 111616
#define SMEM_ATT_COL ((2 * 128 * ASTR + 4 * 64 * ASTR) * 2 + 128 * 4)   // 74240

// ---------------------------------------------------------------------------
// out = LayerNorm(a + b) * g + beta
// ---------------------------------------------------------------------------
__global__ __launch_bounds__(256) void add_ln(
    const float* __restrict__ a, const float* __restrict__ b,
    const float* __restrict__ g, const float* __restrict__ beta,
    float* __restrict__ out)
{
    const int n = blockIdx.x, tid = threadIdx.x;
    const size_t base = (size_t)n * D_;

    float v[3], s = 0.f, ss = 0.f;
#pragma unroll
    for (int t = 0; t < 3; t++) {
        int c = tid + t * 256;
        float x = a[base + c] + b[base + c];
        v[t] = x; s += x; ss += x * x;
    }
#pragma unroll
    for (int off = 16; off > 0; off >>= 1) {
        s  += __shfl_xor_sync(0xffffffffu, s,  off);
        ss += __shfl_xor_sync(0xffffffffu, ss, off);
    }
    __shared__ float sh_s[8], sh_ss[8];
    const int wid = tid >> 5, lane = tid & 31;
    if (lane == 0) { sh_s[wid] = s; sh_ss[wid] = ss; }
    __syncthreads();
    s = 0.f; ss = 0.f;
#pragma unroll
    for (int w = 0; w < 8; w++) { s += sh_s[w]; ss += sh_ss[w]; }

    const float mu  = s * (1.0f / D_);
    const float var = ss * (1.0f / D_) - mu * mu;
    const float r   = rsqrtf(var + EPSLN);
#pragma unroll
    for (int t = 0; t < 3; t++) {
        int c = tid + t * 256;
        out[base + c] = (v[t] - mu) * r * g[c] + beta[c];
    }
}

// ---------------------------------------------------------------------------
extern "C" void kernel_launch(void* const* d_in, const int* in_sizes, int n_in,
                              void* d_out, int out_size)
{
    const float* x     = (const float*)d_in[0];
    const float* w_row = (const float*)d_in[1];
    const float* b_row = (const float*)d_in[2];
    const float* w_col = (const float*)d_in[3];
    const float* b_col = (const float*)d_in[4];
    const float* g1    = (const float*)d_in[5];
    const float* beta1 = (const float*)d_in[6];
    const float* g2    = (const float*)d_in[7];
    const float* beta2 = (const float*)d_in[8];
    const int*   pmask = (const int*)d_in[9];
    float* out = (float*)d_out;

    float *qkv, *tmp;
    cudaGetSymbolAddress((void**)&qkv, g_qkv);
    cudaGetSymbolAddress((void**)&tmp, g_tmp);
    __nv_bfloat16 *ah, *al, *wrh, *wrl, *wch, *wcl;
    cudaGetSymbolAddress((void**)&ah,  g_ah);
    cudaGetSymbolAddress((void**)&al,  g_al);
    cudaGetSymbolAddress((void**)&wrh, g_wrh);
    cudaGetSymbolAddress((void**)&wrl, g_wrl);
    cudaGetSymbolAddress((void**)&wch, g_wch);
    cudaGetSymbolAddress((void**)&wcl, g_wcl);

    cudaFuncSetAttribute(gemm_hmma_x3, cudaFuncAttributeMaxDynamicSharedMemorySize, SMEM_GEMM);
    cudaFuncSetAttribute(attn_mma<2>, cudaFuncAttributeMaxDynamicSharedMemorySize, SMEM_ATT_ROW);
    cudaFuncSetAttribute(attn_mma<1>, cudaFuncAttributeMaxDynamicSharedMemorySize, SMEM_ATT_COL);

    const int nx = N_ * D_;
    const int nw = D3_ * D_;
    dim3 gemm_grid(GM / 128, N_ / 128);

    // splits
    split_f32<<<nw / 1024, 256>>>(w_row, wrh, wrl, nw);
    split_f32<<<nw / 1024, 256>>>(w_col, wch, wcl, nw);
    split_f32<<<nx / 1024, 256>>>(x, ah, al, nx);

    // ---- row pass ----
    gemm_hmma_x3<<<gemm_grid, 256, SMEM_GEMM>>>(ah, al, wrh, wrl, b_row, qkv);
    attn_mma<2><<<dim3(H_, E_), 256, SMEM_ATT_ROW>>>(qkv, pmask, tmp, 0);
    add_ln<<<N_, 256>>>(x, tmp, g1, beta1, out);

    // ---- column pass ----
    split_f32<<<nx / 1024, 256>>>(out, ah, al, nx);
    gemm_hmma_x3<<<gemm_grid, 256, SMEM_GEMM>>>(ah, al, wch, wcl, b_col, qkv);
    attn_mma<1><<<dim3(H_, L_), 256, SMEM_ATT_COL>>>(qkv, pmask, tmp, 1);
    add_ln<<<N_, 256>>>(out, tmp, g2, beta2, out);
}

// round 9
// speedup vs baseline: 4.4915x; 1.1030x over previous
#include <cuda_runtime.h>
#include <cuda_bf16.h>
#include <cstdint>

// Fixed problem shapes
#define B_  1
#define E_  128
#define L_  256
#define H_  12
#define DH_ 64
#define D_  768          // H_*DH_
#define D3_ 2304         // 3*D_
#define N_  32768        // B_*E_*L_
#define EPSLN 1e-5f
#define NEGV  -10000.0f

// Scratch (allocations forbidden -> device globals)
__device__ float g_qkv[(size_t)N_ * D3_];            // 302 MB
__device__ float g_tmp[(size_t)N_ * D_];             // 100 MB
__device__ __nv_bfloat16 g_ah[(size_t)N_ * D_];      // 50 MB
__device__ __nv_bfloat16 g_al[(size_t)N_ * D_];      // 50 MB
__device__ __nv_bfloat16 g_wrh[(size_t)D3_ * D_];
__device__ __nv_bfloat16 g_wrl[(size_t)D3_ * D_];
__device__ __nv_bfloat16 g_wch[(size_t)D3_ * D_];
__device__ __nv_bfloat16 g_wcl[(size_t)D3_ * D_];

// ---------------------------------------------------------------------------
// arch-agnostic PTX helpers (mma.sync / ldmatrix / cp.async)
// ---------------------------------------------------------------------------
__device__ __forceinline__ uint32_t smem_u32(const void* p) {
    uint32_t a;
    asm("{ .reg .u64 t; cvta.to.shared.u64 t, %1; cvt.u32.u64 %0, t; }" : "=r"(a) : "l"(p));
    return a;
}
__device__ __forceinline__ void cp16(uint32_t s, const void* g) {
    asm volatile("cp.async.cg.shared.global [%0], [%1], 16;" :: "r"(s), "l"(g) : "memory");
}
__device__ __forceinline__ void cp_commit() {
    asm volatile("cp.async.commit_group;" ::: "memory");
}
template <int N>
__device__ __forceinline__ void cp_wait() {
    asm volatile("cp.async.wait_group %0;" :: "n"(N) : "memory");
}
__device__ __forceinline__ void ldsm4(uint32_t* r, uint32_t a) {
    asm volatile("ldmatrix.sync.aligned.m8n8.x4.shared.b16 {%0,%1,%2,%3}, [%4];"
                 : "=r"(r[0]), "=r"(r[1]), "=r"(r[2]), "=r"(r[3]) : "r"(a));
}
__device__ __forceinline__ void ldsm2(uint32_t* r, uint32_t a) {
    asm volatile("ldmatrix.sync.aligned.m8n8.x2.shared.b16 {%0,%1}, [%2];"
                 : "=r"(r[0]), "=r"(r[1]) : "r"(a));
}
__device__ __forceinline__ void ldsm2t(uint32_t* r, uint32_t a) {
    asm volatile("ldmatrix.sync.aligned.m8n8.x2.trans.shared.b16 {%0,%1}, [%2];"
                 : "=r"(r[0]), "=r"(r[1]) : "r"(a));
}
__device__ __forceinline__ void mma16816(float* d, const uint32_t* a, const uint32_t* b) {
    asm volatile(
        "mma.sync.aligned.m16n8k16.row.col.f32.bf16.bf16.f32 "
        "{%0,%1,%2,%3}, {%4,%5,%6,%7}, {%8,%9}, {%0,%1,%2,%3};"
        : "+f"(d[0]), "+f"(d[1]), "+f"(d[2]), "+f"(d[3])
        : "r"(a[0]), "r"(a[1]), "r"(a[2]), "r"(a[3]), "r"(b[0]), "r"(b[1]));
}
__device__ __forceinline__ uint32_t pack2(__nv_bfloat16 a, __nv_bfloat16 b) {
    __nv_bfloat162 t = __halves2bfloat162(a, b);
    return *reinterpret_cast<uint32_t*>(&t);
}

// ---------------------------------------------------------------------------
// split: fp32 -> bf16 hi + bf16 lo
// ---------------------------------------------------------------------------
__global__ __launch_bounds__(256) void split_f32(
    const float* __restrict__ in, __nv_bfloat16* __restrict__ hi,
    __nv_bfloat16* __restrict__ lo, int n)
{
    int i = (blockIdx.x * 256 + threadIdx.x) * 4;
    if (i >= n) return;
    float4 v = *(const float4*)(in + i);
    float f[4] = {v.x, v.y, v.z, v.w};
    __nv_bfloat16 h[4], l[4];
#pragma unroll
    for (int q = 0; q < 4; q++) {
        h[q] = __float2bfloat16(f[q]);
        l[q] = __float2bfloat16(f[q] - __bfloat162float(h[q]));
    }
    *(__nv_bfloat162*)(hi + i)     = __halves2bfloat162(h[0], h[1]);
    *(__nv_bfloat162*)(hi + i + 2) = __halves2bfloat162(h[2], h[3]);
    *(__nv_bfloat162*)(lo + i)     = __halves2bfloat162(l[0], l[1]);
    *(__nv_bfloat162*)(lo + i + 2) = __halves2bfloat162(l[2], l[3]);
}

// ---------------------------------------------------------------------------
// bf16 3-way-split GEMM via mma.sync (HMMA).
// minctas=2: cap regs at 128 so 2 CTAs co-reside -> fill MMA bubbles.
// ---------------------------------------------------------------------------
#define GK 768
#define GM 2304
#define BKC 32
#define NIT 24
#define STRD 40
#define BUF_B (128 * STRD * 2)
#define STAGE_B (4 * BUF_B)
#define SMEM_GEMM (2 * STAGE_B)

__device__ __forceinline__ void issue_stage(
    uint32_t smb, int stage, int kc,
    const __nv_bfloat16* __restrict__ pA0, const __nv_bfloat16* __restrict__ pA1,
    const __nv_bfloat16* __restrict__ pB0, const __nv_bfloat16* __restrict__ pB1,
    int tid)
{
    const __nv_bfloat16* src[4] = {pA0, pA1, pB0, pB1};
    const uint32_t sb = smb + (uint32_t)stage * STAGE_B;
#pragma unroll
    for (int buf = 0; buf < 4; buf++) {
#pragma unroll
        for (int i = 0; i < 2; i++) {
            int idx = i * 256 + tid;
            int r = idx >> 2, c16 = idx & 3;
            const void* g = src[buf] + (size_t)r * GK + kc + c16 * 8;
            uint32_t s = sb + (uint32_t)buf * BUF_B + (uint32_t)(r * STRD + c16 * 8) * 2;
            cp16(s, g);
        }
    }
    cp_commit();
}

__global__ __launch_bounds__(256, 2) void gemm_hmma_x3(
    const __nv_bfloat16* __restrict__ Ah, const __nv_bfloat16* __restrict__ Al,
    const __nv_bfloat16* __restrict__ Bh, const __nv_bfloat16* __restrict__ Bl,
    const float* __restrict__ bias, float* __restrict__ C)
{
    extern __shared__ char dynsm[];
    const uint32_t smb = smem_u32(dynsm);

    const int tid  = threadIdx.x;
    const int wid  = tid >> 5, lane = tid & 31;
    const int wm   = wid >> 2;
    const int wn   = wid & 3;
    const int tileN = blockIdx.x;
    const int tileM = blockIdx.y;

    const __nv_bfloat16* pA0 = Ah + (size_t)tileM * 128 * GK;
    const __nv_bfloat16* pA1 = Al + (size_t)tileM * 128 * GK;
    const __nv_bfloat16* pB0 = Bh + (size_t)tileN * 128 * GK;
    const __nv_bfloat16* pB1 = Bl + (size_t)tileN * 128 * GK;

    issue_stage(smb, 0, 0,   pA0, pA1, pB0, pB1, tid);
    issue_stage(smb, 1, BKC, pA0, pA1, pB0, pB1, tid);

    float acc[4][4][4];
#pragma unroll
    for (int a = 0; a < 4; a++)
#pragma unroll
        for (int b = 0; b < 4; b++)
#pragma unroll
            for (int c = 0; c < 4; c++) acc[a][b][c] = 0.f;

    const int aRow = (lane & 15);
    const int aColB = (lane >> 4) * 16;
    const int bRow = (lane & 7);
    const int bColB = ((lane >> 3) & 1) * 16;

    for (int it = 0; it < NIT; it++) {
        if (it < NIT - 2) cp_wait<1>(); else cp_wait<0>();
        __syncthreads();

        const uint32_t sb = smb + (uint32_t)(it & 1) * STAGE_B;
        const uint32_t sAh = sb;
        const uint32_t sAl = sb + BUF_B;
        const uint32_t sBh = sb + 2 * BUF_B;
        const uint32_t sBl = sb + 3 * BUF_B;

#pragma unroll
        for (int ks = 0; ks < 2; ks++) {
            const int kb = ks * 32;
            uint32_t ah[4][4], al4[4][4], bh[4][2], bl[4][2];
#pragma unroll
            for (int mt = 0; mt < 4; mt++) {
                uint32_t off = (uint32_t)((wm * 64 + mt * 16 + aRow) * (STRD * 2) + kb + aColB);
                ldsm4(ah[mt],  sAh + off);
                ldsm4(al4[mt], sAl + off);
            }
#pragma unroll
            for (int nt = 0; nt < 4; nt++) {
                uint32_t off = (uint32_t)((wn * 32 + nt * 8 + bRow) * (STRD * 2) + kb + bColB);
                ldsm2(bh[nt], sBh + off);
                ldsm2(bl[nt], sBl + off);
            }
#pragma unroll
            for (int mt = 0; mt < 4; mt++)
#pragma unroll
                for (int nt = 0; nt < 4; nt++) {
                    mma16816(acc[mt][nt], ah[mt],  bh[nt]);
                    mma16816(acc[mt][nt], ah[mt],  bl[nt]);
                    mma16816(acc[mt][nt], al4[mt], bh[nt]);
                }
        }
        __syncthreads();
        if (it + 2 < NIT)
            issue_stage(smb, it & 1, (it + 2) * BKC, pA0, pA1, pB0, pB1, tid);
    }

    const int r0 = tileM * 128 + wm * 64 + (lane >> 2);
    const int c0 = tileN * 128 + wn * 32 + (lane & 3) * 2;
#pragma unroll
    for (int mt = 0; mt < 4; mt++) {
#pragma unroll
        for (int nt = 0; nt < 4; nt++) {
            const int row = r0 + mt * 16;
            const int col = c0 + nt * 8;
            const float b0 = bias[col], b1 = bias[col + 1];
            float2 v0 = {acc[mt][nt][0] + b0, acc[mt][nt][1] + b1};
            float2 v1 = {acc[mt][nt][2] + b0, acc[mt][nt][3] + b1};
            *(float2*)(C + (size_t)row * GM + col)       = v0;
            *(float2*)(C + (size_t)(row + 8) * GM + col) = v1;
        }
    }
}

// ---------------------------------------------------------------------------
// Flash-style HMMA attention (bf16 3-way split for both QK and PV).
//   row pass: MT=2, grid (12, 128), base = e*256, step = 1
//   col pass: MT=1, grid (12, 256), base = l,     step = 256
// ---------------------------------------------------------------------------
#define ASTR 72
#define ASTRB 144

template <int MT>
__global__ __launch_bounds__(256, 1) void attn_mma(
    const float* __restrict__ qkv, const int* __restrict__ mask,
    float* __restrict__ out, int colmode)
{
    constexpr int NQ  = MT * 128;
    constexpr int NCH = MT * 2;
    extern __shared__ __align__(16) char smraw[];
    __nv_bfloat16* sQh = (__nv_bfloat16*)smraw;
    __nv_bfloat16* sQl = sQh + NQ * ASTR;
    __nv_bfloat16* sKh = sQl + NQ * ASTR;
    __nv_bfloat16* sKl = sKh + 64 * ASTR;
    __nv_bfloat16* sVh = sKl + 64 * ASTR;
    __nv_bfloat16* sVl = sVh + 64 * ASTR;
    float*        negs = (float*)(sVl + 64 * ASTR);

    const int tid  = threadIdx.x;
    const int wid  = tid >> 5, lane = tid & 31;
    const int h    = blockIdx.x;
    const int base = colmode ? (int)blockIdx.y : (int)blockIdx.y * 256;
    const int step = colmode ? 256 : 1;

    const uint32_t uQh = smem_u32(sQh), uQl = smem_u32(sQl);
    const uint32_t uKh = smem_u32(sKh), uKl = smem_u32(sKl);
    const uint32_t uVh = smem_u32(sVh);
    const uint32_t VLOFF = 64 * ASTRB;

    for (int i4 = tid; i4 < NQ * 16; i4 += 256) {
        int r = i4 >> 4, c4 = (i4 & 15) * 4;
        const float* src = qkv + (size_t)(base + r * step) * D3_ + h * 64 + c4;
        float4 v = *(const float4*)src;
        float f[4] = {v.x * 0.125f, v.y * 0.125f, v.z * 0.125f, v.w * 0.125f};
        __nv_bfloat16 hh[4], ll[4];
#pragma unroll
        for (int q = 0; q < 4; q++) {
            hh[q] = __float2bfloat16(f[q]);
            ll[q] = __float2bfloat16(f[q] - __bfloat162float(hh[q]));
        }
        __nv_bfloat162* dh = (__nv_bfloat162*)(sQh + r * ASTR + c4);
        __nv_bfloat162* dl = (__nv_bfloat162*)(sQl + r * ASTR + c4);
        dh[0] = __halves2bfloat162(hh[0], hh[1]); dh[1] = __halves2bfloat162(hh[2], hh[3]);
        dl[0] = __halves2bfloat162(ll[0], ll[1]); dl[1] = __halves2bfloat162(ll[2], ll[3]);
    }
    for (int i = tid; i < NQ; i += 256)
        negs[i] = mask[base + i * step] ? NEGV : 0.f;

    float s[MT][8][4], o[MT][8][4], mrow[MT][2], lrow[MT][2];
#pragma unroll
    for (int mt = 0; mt < MT; mt++) {
        mrow[mt][0] = mrow[mt][1] = -1e30f;
        lrow[mt][0] = lrow[mt][1] = 0.f;
#pragma unroll
        for (int nt = 0; nt < 8; nt++)
#pragma unroll
            for (int c = 0; c < 4; c++) o[mt][nt][c] = 0.f;
    }

    const int aRow  = lane & 15;
    const int aColB = (lane >> 4) * 16;
    const int bRow  = lane & 7;
    const int bColB = ((lane >> 3) & 1) * 16;

    for (int ch = 0; ch < NCH; ch++) {
        float4 kreg[4], vreg[4];
#pragma unroll
        for (int it = 0; it < 4; it++) {
            int i4 = it * 256 + tid;
            int r = i4 >> 4, c4 = (i4 & 15) * 4;
            const float* src = qkv + (size_t)(base + (ch * 64 + r) * step) * D3_ + h * 64 + c4;
            kreg[it] = *(const float4*)(src + 768);
            vreg[it] = *(const float4*)(src + 1536);
        }
        __syncthreads();
#pragma unroll
        for (int it = 0; it < 4; it++) {
            int i4 = it * 256 + tid;
            int r = i4 >> 4, c4 = (i4 & 15) * 4;
            float fk[4] = {kreg[it].x, kreg[it].y, kreg[it].z, kreg[it].w};
            float fv[4] = {vreg[it].x, vreg[it].y, vreg[it].z, vreg[it].w};
            __nv_bfloat16 kh[4], kl[4], vh[4], vl[4];
#pragma unroll
            for (int q = 0; q < 4; q++) {
                kh[q] = __float2bfloat16(fk[q]);
                kl[q] = __float2bfloat16(fk[q] - __bfloat162float(kh[q]));
                vh[q] = __float2bfloat16(fv[q]);
                vl[q] = __float2bfloat16(fv[q] - __bfloat162float(vh[q]));
            }
            __nv_bfloat162* dkh = (__nv_bfloat162*)(sKh + r * ASTR + c4);
            __nv_bfloat162* dkl = (__nv_bfloat162*)(sKl + r * ASTR + c4);
            __nv_bfloat162* dvh = (__nv_bfloat162*)(sVh + r * ASTR + c4);
            __nv_bfloat162* dvl = (__nv_bfloat162*)(sVl + r * ASTR + c4);
            dkh[0] = __halves2bfloat162(kh[0], kh[1]); dkh[1] = __halves2bfloat162(kh[2], kh[3]);
            dkl[0] = __halves2bfloat162(kl[0], kl[1]); dkl[1] = __halves2bfloat162(kl[2], kl[3]);
            dvh[0] = __halves2bfloat162(vh[0], vh[1]); dvh[1] = __halves2bfloat162(vh[2], vh[3]);
            dvl[0] = __halves2bfloat162(vl[0], vl[1]); dvl[1] = __halves2bfloat162(vl[2], vl[3]);
        }
        __syncthreads();

#pragma unroll
        for (int mt = 0; mt < MT; mt++)
#pragma unroll
            for (int nt = 0; nt < 8; nt++)
#pragma unroll
                for (int c = 0; c < 4; c++) s[mt][nt][c] = 0.f;

#pragma unroll
        for (int kq = 0; kq < 4; kq++) {
            uint32_t ah[MT][4], al[MT][4];
#pragma unroll
            for (int mt = 0; mt < MT; mt++) {
                uint32_t off = (uint32_t)((wid * (MT * 16) + mt * 16 + aRow) * ASTRB
                                          + kq * 32 + aColB);
                ldsm4(ah[mt], uQh + off);
                ldsm4(al[mt], uQl + off);
            }
#pragma unroll
            for (int nt = 0; nt < 8; nt++) {
                uint32_t kbh[2], kbl[2];
                uint32_t off = (uint32_t)((nt * 8 + bRow) * ASTRB + kq * 32 + bColB);
                ldsm2(kbh, uKh + off);
                ldsm2(kbl, uKl + off);
#pragma unroll
                for (int mt = 0; mt < MT; mt++) {
                    mma16816(s[mt][nt], ah[mt], kbh);
                    mma16816(s[mt][nt], ah[mt], kbl);
                    mma16816(s[mt][nt], al[mt], kbh);
                }
            }
        }

#pragma unroll
        for (int nt = 0; nt < 8; nt++) {
            int j = ch * 64 + nt * 8 + (lane & 3) * 2;
            float n0 = negs[j], n1 = negs[j + 1];
#pragma unroll
            for (int mt = 0; mt < MT; mt++) {
                s[mt][nt][0] += n0; s[mt][nt][1] += n1;
                s[mt][nt][2] += n0; s[mt][nt][3] += n1;
            }
        }
#pragma unroll
        for (int mt = 0; mt < MT; mt++) {
#pragma unroll
            for (int hf = 0; hf < 2; hf++) {
                float rm = -1e30f;
#pragma unroll
                for (int nt = 0; nt < 8; nt++)
                    rm = fmaxf(rm, fmaxf(s[mt][nt][2 * hf], s[mt][nt][2 * hf + 1]));
                rm = fmaxf(rm, __shfl_xor_sync(0xffffffffu, rm, 1));
                rm = fmaxf(rm, __shfl_xor_sync(0xffffffffu, rm, 2));
                float mo = mrow[mt][hf];
                float mn = fmaxf(mo, rm);
                float corr = __expf(mo - mn);
                float rs = 0.f;
#pragma unroll
                for (int nt = 0; nt < 8; nt++) {
                    float p0 = __expf(s[mt][nt][2 * hf]     - mn);
                    float p1 = __expf(s[mt][nt][2 * hf + 1] - mn);
                    s[mt][nt][2 * hf] = p0; s[mt][nt][2 * hf + 1] = p1;
                    rs += p0 + p1;
                    o[mt][nt][2 * hf] *= corr; o[mt][nt][2 * hf + 1] *= corr;
                }
                rs += __shfl_xor_sync(0xffffffffu, rs, 1);
                rs += __shfl_xor_sync(0xffffffffu, rs, 2);
                lrow[mt][hf] = lrow[mt][hf] * corr + rs;
                mrow[mt][hf] = mn;
            }
        }

#pragma unroll
        for (int kk = 0; kk < 4; kk++) {
            uint32_t pah[MT][4], pal[MT][4];
#pragma unroll
            for (int mt = 0; mt < MT; mt++) {
#pragma unroll
                for (int q = 0; q < 4; q++) {
                    int nt = kk * 2 + (q >> 1);
                    int i0 = (q & 1) * 2;
                    float p0 = s[mt][nt][i0], p1 = s[mt][nt][i0 + 1];
                    __nv_bfloat16 h0 = __float2bfloat16(p0);
                    __nv_bfloat16 h1 = __float2bfloat16(p1);
                    pah[mt][q] = pack2(h0, h1);
                    __nv_bfloat16 l0 = __float2bfloat16(p0 - __bfloat162float(h0));
                    __nv_bfloat16 l1 = __float2bfloat16(p1 - __bfloat162float(h1));
                    pal[mt][q] = pack2(l0, l1);
                }
            }
#pragma unroll
            for (int nt = 0; nt < 8; nt++) {
                uint32_t vbh[2], vbl[2];
                uint32_t va = uVh + (uint32_t)((kk * 16 + (lane & 15)) * ASTRB + nt * 16);
                ldsm2t(vbh, va);
                ldsm2t(vbl, va + VLOFF);
#pragma unroll
                for (int mt = 0; mt < MT; mt++) {
                    mma16816(o[mt][nt], pah[mt], vbh);
                    mma16816(o[mt][nt], pah[mt], vbl);
                    mma16816(o[mt][nt], pal[mt], vbh);
                }
            }
        }
    }

#pragma unroll
    for (int mt = 0; mt < MT; mt++) {
#pragma unroll
        for (int hf = 0; hf < 2; hf++) {
            float inv = 1.f / lrow[mt][hf];
            int qrow = wid * (MT * 16) + mt * 16 + hf * 8 + (lane >> 2);
            size_t ob = (size_t)(base + qrow * step) * D_ + h * 64 + (lane & 3) * 2;
#pragma unroll
            for (int nt = 0; nt < 8; nt++) {
                float2 v = {o[mt][nt][2 * hf] * inv, o[mt][nt][2 * hf + 1] * inv};
                *(float2*)(out + ob + nt * 8) = v;
            }
        }
    }
}

#define SMEM_ATT_ROW ((2 * 256 * ASTR + 4 * 64 * ASTR) * 2 + 256 * 4)
#define SMEM_ATT_COL ((2 * 128 * ASTR + 4 * 64 * ASTR) * 2 + 128 * 4)

// ---------------------------------------------------------------------------
// out = LayerNorm(a + b) * g + beta, optionally also emit bf16 hi/lo split
// ---------------------------------------------------------------------------
template <int SPLIT>
__global__ __launch_bounds__(256) void add_ln_t(
    const float* __restrict__ a, const float* __restrict__ b,
    const float* __restrict__ g, const float* __restrict__ beta,
    float* __restrict__ out, __nv_bfloat16* __restrict__ hi,
    __nv_bfloat16* __restrict__ lo)
{
    const int n = blockIdx.x, tid = threadIdx.x;
    const size_t base = (size_t)n * D_;

    float v[3], s = 0.f, ss = 0.f;
#pragma unroll
    for (int t = 0; t < 3; t++) {
        int c = tid + t * 256;
        float x = a[base + c] + b[base + c];
        v[t] = x; s += x; ss += x * x;
    }
#pragma unroll
    for (int off = 16; off > 0; off >>= 1) {
        s  += __shfl_xor_sync(0xffffffffu, s,  off);
        ss += __shfl_xor_sync(0xffffffffu, ss, off);
    }
    __shared__ float sh_s[8], sh_ss[8];
    const int wid = tid >> 5, lane = tid & 31;
    if (lane == 0) { sh_s[wid] = s; sh_ss[wid] = ss; }
    __syncthreads();
    s = 0.f; ss = 0.f;
#pragma unroll
    for (int w = 0; w < 8; w++) { s += sh_s[w]; ss += sh_ss[w]; }

    const float mu  = s * (1.0f / D_);
    const float var = ss * (1.0f / D_) - mu * mu;
    const float r   = rsqrtf(var + EPSLN);
#pragma unroll
    for (int t = 0; t < 3; t++) {
        int c = tid + t * 256;
        float y = (v[t] - mu) * r * g[c] + beta[c];
        out[base + c] = y;
        if (SPLIT) {
            __nv_bfloat16 hh = __float2bfloat16(y);
            hi[base + c] = hh;
            lo[base + c] = __float2bfloat16(y - __bfloat162float(hh));
        }
    }
}

// ---------------------------------------------------------------------------
extern "C" void kernel_launch(void* const* d_in, const int* in_sizes, int n_in,
                              void* d_out, int out_size)
{
    const float* x     = (const float*)d_in[0];
    const float* w_row = (const float*)d_in[1];
    const float* b_row = (const float*)d_in[2];
    const float* w_col = (const float*)d_in[3];
    const float* b_col = (const float*)d_in[4];
    const float* g1    = (const float*)d_in[5];
    const float* beta1 = (const float*)d_in[6];
    const float* g2    = (const float*)d_in[7];
    const float* beta2 = (const float*)d_in[8];
    const int*   pmask = (const int*)d_in[9];
    float* out = (float*)d_out;

    float *qkv, *tmp;
    cudaGetSymbolAddress((void**)&qkv, g_qkv);
    cudaGetSymbolAddress((void**)&tmp, g_tmp);
    __nv_bfloat16 *ah, *al, *wrh, *wrl, *wch, *wcl;
    cudaGetSymbolAddress((void**)&ah,  g_ah);
    cudaGetSymbolAddress((void**)&al,  g_al);
    cudaGetSymbolAddress((void**)&wrh, g_wrh);
    cudaGetSymbolAddress((void**)&wrl, g_wrl);
    cudaGetSymbolAddress((void**)&wch, g_wch);
    cudaGetSymbolAddress((void**)&wcl, g_wcl);

    cudaFuncSetAttribute(gemm_hmma_x3, cudaFuncAttributeMaxDynamicSharedMemorySize, SMEM_GEMM);
    cudaFuncSetAttribute(attn_mma<2>, cudaFuncAttributeMaxDynamicSharedMemorySize, SMEM_ATT_ROW);
    cudaFuncSetAttribute(attn_mma<1>, cudaFuncAttributeMaxDynamicSharedMemorySize, SMEM_ATT_COL);

    const int nx = N_ * D_;
    const int nw = D3_ * D_;
    dim3 gemm_grid(GM / 128, N_ / 128);

    // splits (weights + x)
    split_f32<<<nw / 1024, 256>>>(w_row, wrh, wrl, nw);
    split_f32<<<nw / 1024, 256>>>(w_col, wch, wcl, nw);
    split_f32<<<nx / 1024, 256>>>(x, ah, al, nx);

    // ---- row pass ----
    gemm_hmma_x3<<<gemm_grid, 256, SMEM_GEMM>>>(ah, al, wrh, wrl, b_row, qkv);
    attn_mma<2><<<dim3(H_, E_), 256, SMEM_ATT_ROW>>>(qkv, pmask, tmp, 0);
    add_ln_t<1><<<N_, 256>>>(x, tmp, g1, beta1, out, ah, al);   // fused split

    // ---- column pass ----
    gemm_hmma_x3<<<gemm_grid, 256, SMEM_GEMM>>>(ah, al, wch, wcl, b_col, qkv);
    attn_mma<1><<<dim3(H_, L_), 256, SMEM_ATT_COL>>>(qkv, pmask, tmp, 1);
    add_ln_t<0><<<N_, 256>>>(out, tmp, g2, beta2, out, nullptr, nullptr);
}

// round 11
// speedup vs baseline: 5.2570x; 1.1704x over previous
#include <cuda_runtime.h>
#include <cuda_bf16.h>
#include <cstdint>

// Fixed problem shapes
#define B_  1
#define E_  128
#define L_  256
#define H_  12
#define DH_ 64
#define D_  768          // H_*DH_
#define D3_ 2304         // 3*D_
#define N_  32768        // B_*E_*L_
#define EPSLN 1e-5f
#define NEGV  -10000.0f

// Scratch (allocations forbidden -> device globals)
__device__ float g_qkv[(size_t)N_ * D3_];            // 302 MB
__device__ float g_tmp[(size_t)N_ * D_];             // 100 MB
__device__ __nv_bfloat16 g_ah[(size_t)N_ * D_];      // 50 MB
__device__ __nv_bfloat16 g_al[(size_t)N_ * D_];      // 50 MB
__device__ __nv_bfloat16 g_wrh[(size_t)D3_ * D_];
__device__ __nv_bfloat16 g_wrl[(size_t)D3_ * D_];
__device__ __nv_bfloat16 g_wch[(size_t)D3_ * D_];
__device__ __nv_bfloat16 g_wcl[(size_t)D3_ * D_];

// ---------------------------------------------------------------------------
// arch-agnostic PTX helpers
// ---------------------------------------------------------------------------
__device__ __forceinline__ uint32_t smem_u32(const void* p) {
    uint32_t a;
    asm("{ .reg .u64 t; cvta.to.shared.u64 t, %1; cvt.u32.u64 %0, t; }" : "=r"(a) : "l"(p));
    return a;
}
__device__ __forceinline__ void cp16(uint32_t s, const void* g) {
    asm volatile("cp.async.cg.shared.global [%0], [%1], 16;" :: "r"(s), "l"(g) : "memory");
}
__device__ __forceinline__ void cp_commit() {
    asm volatile("cp.async.commit_group;" ::: "memory");
}
template <int N>
__device__ __forceinline__ void cp_wait() {
    asm volatile("cp.async.wait_group %0;" :: "n"(N) : "memory");
}
__device__ __forceinline__ void ldsm4(uint32_t* r, uint32_t a) {
    asm volatile("ldmatrix.sync.aligned.m8n8.x4.shared.b16 {%0,%1,%2,%3}, [%4];"
                 : "=r"(r[0]), "=r"(r[1]), "=r"(r[2]), "=r"(r[3]) : "r"(a));
}
__device__ __forceinline__ void ldsm2(uint32_t* r, uint32_t a) {
    asm volatile("ldmatrix.sync.aligned.m8n8.x2.shared.b16 {%0,%1}, [%2];"
                 : "=r"(r[0]), "=r"(r[1]) : "r"(a));
}
__device__ __forceinline__ void ldsm2t(uint32_t* r, uint32_t a) {
    asm volatile("ldmatrix.sync.aligned.m8n8.x2.trans.shared.b16 {%0,%1}, [%2];"
                 : "=r"(r[0]), "=r"(r[1]) : "r"(a));
}
__device__ __forceinline__ void mma16816(float* d, const uint32_t* a, const uint32_t* b) {
    asm volatile(
        "mma.sync.aligned.m16n8k16.row.col.f32.bf16.bf16.f32 "
        "{%0,%1,%2,%3}, {%4,%5,%6,%7}, {%8,%9}, {%0,%1,%2,%3};"
        : "+f"(d[0]), "+f"(d[1]), "+f"(d[2]), "+f"(d[3])
        : "r"(a[0]), "r"(a[1]), "r"(a[2]), "r"(a[3]), "r"(b[0]), "r"(b[1]));
}
__device__ __forceinline__ uint32_t pack2(__nv_bfloat16 a, __nv_bfloat16 b) {
    __nv_bfloat162 t = __halves2bfloat162(a, b);
    return *reinterpret_cast<uint32_t*>(&t);
}
__device__ __forceinline__ uint32_t sw128(uint32_t off) {
    return off ^ ((off >> 3) & 0x70);
}

// ---------------------------------------------------------------------------
// split: fp32 -> bf16 hi + bf16 lo
// ---------------------------------------------------------------------------
__global__ __launch_bounds__(256) void split_f32(
    const float* __restrict__ in, __nv_bfloat16* __restrict__ hi,
    __nv_bfloat16* __restrict__ lo, int n)
{
    int i = (blockIdx.x * 256 + threadIdx.x) * 4;
    if (i >= n) return;
    float4 v = *(const float4*)(in + i);
    float f[4] = {v.x, v.y, v.z, v.w};
    __nv_bfloat16 h[4], l[4];
#pragma unroll
    for (int q = 0; q < 4; q++) {
        h[q] = __float2bfloat16(f[q]);
        l[q] = __float2bfloat16(f[q] - __bfloat162float(h[q]));
    }
    *(__nv_bfloat162*)(hi + i)     = __halves2bfloat162(h[0], h[1]);
    *(__nv_bfloat162*)(hi + i + 2) = __halves2bfloat162(h[2], h[3]);
    *(__nv_bfloat162*)(lo + i)     = __halves2bfloat162(l[0], l[1]);
    *(__nv_bfloat162*)(lo + i + 2) = __halves2bfloat162(l[2], l[3]);
}

// ---------------------------------------------------------------------------
// bf16 3-way-split GEMM via mma.sync (HMMA).
// SW128 interleaved hi|lo rows (128B), 3-stage cp.async pipeline, ONE sync/iter.
// CTA 128x128, BK=32, 8 warps (2x4), warp tile 64x32. 2 CTAs/SM.
// ---------------------------------------------------------------------------
#define GK 768
#define GM 2304
#define BKC 32
#define NIT 24
#define ABUF_B 16384                 // 128 rows x 128B (hi|lo interleaved)
#define STG_B  (2 * ABUF_B)          // A buf + B buf = 32 KB
#define SMEM_GEMM (3 * STG_B + 1024) // 3 stages + align slack

__device__ __forceinline__ void issue_stage3(
    uint32_t sbase, int kc,
    const __nv_bfloat16* __restrict__ pAh, const __nv_bfloat16* __restrict__ pAl,
    const __nv_bfloat16* __restrict__ pBh, const __nv_bfloat16* __restrict__ pBl,
    int tid)
{
#pragma unroll
    for (int i = 0; i < 4; i++) {
        int idx = i * 256 + tid;             // 0..1023
        int r = idx >> 3, half = (idx >> 2) & 1, c16 = idx & 3;
        const __nv_bfloat16* g = (half ? pAl : pAh) + (size_t)r * GK + kc + c16 * 8;
        uint32_t off = (uint32_t)(r * 128 + half * 64 + c16 * 16);
        cp16(sbase + sw128(off), g);
    }
#pragma unroll
    for (int i = 0; i < 4; i++) {
        int idx = i * 256 + tid;
        int r = idx >> 3, half = (idx >> 2) & 1, c16 = idx & 3;
        const __nv_bfloat16* g = (half ? pBl : pBh) + (size_t)r * GK + kc + c16 * 8;
        uint32_t off = (uint32_t)(r * 128 + half * 64 + c16 * 16);
        cp16(sbase + ABUF_B + sw128(off), g);
    }
    cp_commit();
}

__global__ __launch_bounds__(256, 2) void gemm_hmma_x3(
    const __nv_bfloat16* __restrict__ Ah, const __nv_bfloat16* __restrict__ Al,
    const __nv_bfloat16* __restrict__ Bh, const __nv_bfloat16* __restrict__ Bl,
    const float* __restrict__ bias, float* __restrict__ C)
{
    extern __shared__ char dynsm[];
    uint32_t smb = smem_u32(dynsm);
    smb = (smb + 1023u) & ~1023u;

    const int tid  = threadIdx.x;
    const int wid  = tid >> 5, lane = tid & 31;
    const int wm   = wid >> 2;        // 0..1
    const int wn   = wid & 3;         // 0..3
    const int tileN = blockIdx.x;
    const int tileM = blockIdx.y;

    const __nv_bfloat16* pA0 = Ah + (size_t)tileM * 128 * GK;
    const __nv_bfloat16* pA1 = Al + (size_t)tileM * 128 * GK;
    const __nv_bfloat16* pB0 = Bh + (size_t)tileN * 128 * GK;
    const __nv_bfloat16* pB1 = Bl + (size_t)tileN * 128 * GK;

    issue_stage3(smb + 0 * STG_B, 0 * BKC, pA0, pA1, pB0, pB1, tid);
    issue_stage3(smb + 1 * STG_B, 1 * BKC, pA0, pA1, pB0, pB1, tid);

    float acc[4][4][4];
#pragma unroll
    for (int a = 0; a < 4; a++)
#pragma unroll
        for (int b = 0; b < 4; b++)
#pragma unroll
            for (int c = 0; c < 4; c++) acc[a][b][c] = 0.f;

    // per-lane ldmatrix address components
    const int aRow  = lane & 15;              // A rows
    const int aColB = (lane >> 4) * 16;       // A k halves
    const int grp   = lane >> 3;              // B groups for ldsm4
    const int bRow  = ((grp >> 1) * 8) + (lane & 7);
    const int bColB = (grp & 1) * 16;

    int st = 0;
    for (int it = 0; it < NIT; it++) {
        if (it < NIT - 2) cp_wait<1>(); else cp_wait<0>();
        __syncthreads();

        // prefetch stage (it+2) — its prior readers all passed the barrier above
        if (it + 2 < NIT) {
            int stn = st + 2; if (stn >= 3) stn -= 3;
            issue_stage3(smb + (uint32_t)stn * STG_B, (it + 2) * BKC,
                         pA0, pA1, pB0, pB1, tid);
        }

        const uint32_t sA = smb + (uint32_t)st * STG_B;
        const uint32_t sB = sA + ABUF_B;

#pragma unroll
        for (int ks = 0; ks < 2; ks++) {
            const int kb = ks * 32;           // byte offset of k16 step
            uint32_t ah[4][4], al4[4][4], bh4[2][4], bl4[2][4];
#pragma unroll
            for (int mt = 0; mt < 4; mt++) {
                uint32_t off = (uint32_t)((wm * 64 + mt * 16 + aRow) * 128 + kb + aColB);
                ldsm4(ah[mt],  sA + sw128(off));
                ldsm4(al4[mt], sA + sw128(off + 64));
            }
#pragma unroll
            for (int pr = 0; pr < 2; pr++) {
                uint32_t off = (uint32_t)((wn * 32 + pr * 16 + bRow) * 128 + kb + bColB);
                ldsm4(bh4[pr], sB + sw128(off));
                ldsm4(bl4[pr], sB + sw128(off + 64));
            }
#pragma unroll
            for (int mt = 0; mt < 4; mt++)
#pragma unroll
                for (int pr = 0; pr < 2; pr++)
#pragma unroll
                    for (int half = 0; half < 2; half++) {
                        const int nt = pr * 2 + half;
                        mma16816(acc[mt][nt], ah[mt],  &bh4[pr][half * 2]);
                        mma16816(acc[mt][nt], ah[mt],  &bl4[pr][half * 2]);
                        mma16816(acc[mt][nt], al4[mt], &bh4[pr][half * 2]);
                    }
        }
        st++; if (st == 3) st = 0;
    }

    const int r0 = tileM * 128 + wm * 64 + (lane >> 2);
    const int c0 = tileN * 128 + wn * 32 + (lane & 3) * 2;
#pragma unroll
    for (int mt = 0; mt < 4; mt++) {
#pragma unroll
        for (int nt = 0; nt < 4; nt++) {
            const int row = r0 + mt * 16;
            const int col = c0 + nt * 8;
            const float b0 = bias[col], b1 = bias[col + 1];
            float2 v0 = {acc[mt][nt][0] + b0, acc[mt][nt][1] + b1};
            float2 v1 = {acc[mt][nt][2] + b0, acc[mt][nt][3] + b1};
            *(float2*)(C + (size_t)row * GM + col)       = v0;
            *(float2*)(C + (size_t)(row + 8) * GM + col) = v1;
        }
    }
}

// ---------------------------------------------------------------------------
// Flash-style HMMA attention (bf16 3-way split for both QK and PV).
//   row pass: MT=2, grid (12, 128), base = e*256, step = 1
//   col pass: MT=1, grid (12, 256), base = l,     step = 256
// ---------------------------------------------------------------------------
#define ASTR 72
#define ASTRB 144

template <int MT>
__global__ __launch_bounds__(256, 1) void attn_mma(
    const float* __restrict__ qkv, const int* __restrict__ mask,
    float* __restrict__ out, int colmode)
{
    constexpr int NQ  = MT * 128;
    constexpr int NCH = MT * 2;
    extern __shared__ __align__(16) char smraw[];
    __nv_bfloat16* sQh = (__nv_bfloat16*)smraw;
    __nv_bfloat16* sQl = sQh + NQ * ASTR;
    __nv_bfloat16* sKh = sQl + NQ * ASTR;
    __nv_bfloat16* sKl = sKh + 64 * ASTR;
    __nv_bfloat16* sVh = sKl + 64 * ASTR;
    __nv_bfloat16* sVl = sVh + 64 * ASTR;
    float*        negs = (float*)(sVl + 64 * ASTR);

    const int tid  = threadIdx.x;
    const int wid  = tid >> 5, lane = tid & 31;
    const int h    = blockIdx.x;
    const int base = colmode ? (int)blockIdx.y : (int)blockIdx.y * 256;
    const int step = colmode ? 256 : 1;

    const uint32_t uQh = smem_u32(sQh), uQl = smem_u32(sQl);
    const uint32_t uKh = smem_u32(sKh), uKl = smem_u32(sKl);
    const uint32_t uVh = smem_u32(sVh);
    const uint32_t VLOFF = 64 * ASTRB;

    for (int i4 = tid; i4 < NQ * 16; i4 += 256) {
        int r = i4 >> 4, c4 = (i4 & 15) * 4;
        const float* src = qkv + (size_t)(base + r * step) * D3_ + h * 64 + c4;
        float4 v = *(const float4*)src;
        float f[4] = {v.x * 0.125f, v.y * 0.125f, v.z * 0.125f, v.w * 0.125f};
        __nv_bfloat16 hh[4], ll[4];
#pragma unroll
        for (int q = 0; q < 4; q++) {
            hh[q] = __float2bfloat16(f[q]);
            ll[q] = __float2bfloat16(f[q] - __bfloat162float(hh[q]));
        }
        __nv_bfloat162* dh = (__nv_bfloat162*)(sQh + r * ASTR + c4);
        __nv_bfloat162* dl = (__nv_bfloat162*)(sQl + r * ASTR + c4);
        dh[0] = __halves2bfloat162(hh[0], hh[1]); dh[1] = __halves2bfloat162(hh[2], hh[3]);
        dl[0] = __halves2bfloat162(ll[0], ll[1]); dl[1] = __halves2bfloat162(ll[2], ll[3]);
    }
    for (int i = tid; i < NQ; i += 256)
        negs[i] = mask[base + i * step] ? NEGV : 0.f;

    float s[MT][8][4], o[MT][8][4], mrow[MT][2], lrow[MT][2];
#pragma unroll
    for (int mt = 0; mt < MT; mt++) {
        mrow[mt][0] = mrow[mt][1] = -1e30f;
        lrow[mt][0] = lrow[mt][1] = 0.f;
#pragma unroll
        for (int nt = 0; nt < 8; nt++)
#pragma unroll
            for (int c = 0; c < 4; c++) o[mt][nt][c] = 0.f;
    }

    const int aRow  = lane & 15;
    const int aColB = (lane >> 4) * 16;
    const int bRow  = lane & 7;
    const int bColB = ((lane >> 3) & 1) * 16;

    for (int ch = 0; ch < NCH; ch++) {
        float4 kreg[4], vreg[4];
#pragma unroll
        for (int it = 0; it < 4; it++) {
            int i4 = it * 256 + tid;
            int r = i4 >> 4, c4 = (i4 & 15) * 4;
            const float* src = qkv + (size_t)(base + (ch * 64 + r) * step) * D3_ + h * 64 + c4;
            kreg[it] = *(const float4*)(src + 768);
            vreg[it] = *(const float4*)(src + 1536);
        }
        __syncthreads();
#pragma unroll
        for (int it = 0; it < 4; it++) {
            int i4 = it * 256 + tid;
            int r = i4 >> 4, c4 = (i4 & 15) * 4;
            float fk[4] = {kreg[it].x, kreg[it].y, kreg[it].z, kreg[it].w};
            float fv[4] = {vreg[it].x, vreg[it].y, vreg[it].z, vreg[it].w};
            __nv_bfloat16 kh[4], kl[4], vh[4], vl[4];
#pragma unroll
            for (int q = 0; q < 4; q++) {
                kh[q] = __float2bfloat16(fk[q]);
                kl[q] = __float2bfloat16(fk[q] - __bfloat162float(kh[q]));
                vh[q] = __float2bfloat16(fv[q]);
                vl[q] = __float2bfloat16(fv[q] - __bfloat162float(vh[q]));
            }
            __nv_bfloat162* dkh = (__nv_bfloat162*)(sKh + r * ASTR + c4);
            __nv_bfloat162* dkl = (__nv_bfloat162*)(sKl + r * ASTR + c4);
            __nv_bfloat162* dvh = (__nv_bfloat162*)(sVh + r * ASTR + c4);
            __nv_bfloat162* dvl = (__nv_bfloat162*)(sVl + r * ASTR + c4);
            dkh[0] = __halves2bfloat162(kh[0], kh[1]); dkh[1] = __halves2bfloat162(kh[2], kh[3]);
            dkl[0] = __halves2bfloat162(kl[0], kl[1]); dkl[1] = __halves2bfloat162(kl[2], kl[3]);
            dvh[0] = __halves2bfloat162(vh[0], vh[1]); dvh[1] = __halves2bfloat162(vh[2], vh[3]);
            dvl[0] = __halves2bfloat162(vl[0], vl[1]); dvl[1] = __halves2bfloat162(vl[2], vl[3]);
        }
        __syncthreads();

#pragma unroll
        for (int mt = 0; mt < MT; mt++)
#pragma unroll
            for (int nt = 0; nt < 8; nt++)
#pragma unroll
                for (int c = 0; c < 4; c++) s[mt][nt][c] = 0.f;

#pragma unroll
        for (int kq = 0; kq < 4; kq++) {
            uint32_t ah[MT][4], al[MT][4];
#pragma unroll
            for (int mt = 0; mt < MT; mt++) {
                uint32_t off = (uint32_t)((wid * (MT * 16) + mt * 16 + aRow) * ASTRB
                                          + kq * 32 + aColB);
                ldsm4(ah[mt], uQh + off);
                ldsm4(al[mt], uQl + off);
            }
#pragma unroll
            for (int nt = 0; nt < 8; nt++) {
                uint32_t kbh[2], kbl[2];
                uint32_t off = (uint32_t)((nt * 8 + bRow) * ASTRB + kq * 32 + bColB);
                ldsm2(kbh, uKh + off);
                ldsm2(kbl, uKl + off);
#pragma unroll
                for (int mt = 0; mt < MT; mt++) {
                    mma16816(s[mt][nt], ah[mt], kbh);
                    mma16816(s[mt][nt], ah[mt], kbl);
                    mma16816(s[mt][nt], al[mt], kbh);
                }
            }
        }

#pragma unroll
        for (int nt = 0; nt < 8; nt++) {
            int j = ch * 64 + nt * 8 + (lane & 3) * 2;
            float n0 = negs[j], n1 = negs[j + 1];
#pragma unroll
            for (int mt = 0; mt < MT; mt++) {
                s[mt][nt][0] += n0; s[mt][nt][1] += n1;
                s[mt][nt][2] += n0; s[mt][nt][3] += n1;
            }
        }
#pragma unroll
        for (int mt = 0; mt < MT; mt++) {
#pragma unroll
            for (int hf = 0; hf < 2; hf++) {
                float rm = -1e30f;
#pragma unroll
                for (int nt = 0; nt < 8; nt++)
                    rm = fmaxf(rm, fmaxf(s[mt][nt][2 * hf], s[mt][nt][2 * hf + 1]));
                rm = fmaxf(rm, __shfl_xor_sync(0xffffffffu, rm, 1));
                rm = fmaxf(rm, __shfl_xor_sync(0xffffffffu, rm, 2));
                float mo = mrow[mt][hf];
                float mn = fmaxf(mo, rm);
                float corr = __expf(mo - mn);
                float rs = 0.f;
#pragma unroll
                for (int nt = 0; nt < 8; nt++) {
                    float p0 = __expf(s[mt][nt][2 * hf]     - mn);
                    float p1 = __expf(s[mt][nt][2 * hf + 1] - mn);
                    s[mt][nt][2 * hf] = p0; s[mt][nt][2 * hf + 1] = p1;
                    rs += p0 + p1;
                    o[mt][nt][2 * hf] *= corr; o[mt][nt][2 * hf + 1] *= corr;
                }
                rs += __shfl_xor_sync(0xffffffffu, rs, 1);
                rs += __shfl_xor_sync(0xffffffffu, rs, 2);
                lrow[mt][hf] = lrow[mt][hf] * corr + rs;
                mrow[mt][hf] = mn;
            }
        }

#pragma unroll
        for (int kk = 0; kk < 4; kk++) {
            uint32_t pah[MT][4], pal[MT][4];
#pragma unroll
            for (int mt = 0; mt < MT; mt++) {
#pragma unroll
                for (int q = 0; q < 4; q++) {
                    int nt = kk * 2 + (q >> 1);
                    int i0 = (q & 1) * 2;
                    float p0 = s[mt][nt][i0], p1 = s[mt][nt][i0 + 1];
                    __nv_bfloat16 h0 = __float2bfloat16(p0);
                    __nv_bfloat16 h1 = __float2bfloat16(p1);
                    pah[mt][q] = pack2(h0, h1);
                    __nv_bfloat16 l0 = __float2bfloat16(p0 - __bfloat162float(h0));
                    __nv_bfloat16 l1 = __float2bfloat16(p1 - __bfloat162float(h1));
                    pal[mt][q] = pack2(l0, l1);
                }
            }
#pragma unroll
            for (int nt = 0; nt < 8; nt++) {
                uint32_t vbh[2], vbl[2];
                uint32_t va = uVh + (uint32_t)((kk * 16 + (lane & 15)) * ASTRB + nt * 16);
                ldsm2t(vbh, va);
                ldsm2t(vbl, va + VLOFF);
#pragma unroll
                for (int mt = 0; mt < MT; mt++) {
                    mma16816(o[mt][nt], pah[mt], vbh);
                    mma16816(o[mt][nt], pah[mt], vbl);
                    mma16816(o[mt][nt], pal[mt], vbh);
                }
            }
        }
    }

#pragma unroll
    for (int mt = 0; mt < MT; mt++) {
#pragma unroll
        for (int hf = 0; hf < 2; hf++) {
            float inv = 1.f / lrow[mt][hf];
            int qrow = wid * (MT * 16) + mt * 16 + hf * 8 + (lane >> 2);
            size_t ob = (size_t)(base + qrow * step) * D_ + h * 64 + (lane & 3) * 2;
#pragma unroll
            for (int nt = 0; nt < 8; nt++) {
                float2 v = {o[mt][nt][2 * hf] * inv, o[mt][nt][2 * hf + 1] * inv};
                *(float2*)(out + ob + nt * 8) = v;
            }
        }
    }
}

#define SMEM_ATT_ROW ((2 * 256 * ASTR + 4 * 64 * ASTR) * 2 + 256 * 4)
#define SMEM_ATT_COL ((2 * 128 * ASTR + 4 * 64 * ASTR) * 2 + 128 * 4)

// ---------------------------------------------------------------------------
// out = LayerNorm(a + b) * g + beta, optionally also emit bf16 hi/lo split
// ---------------------------------------------------------------------------
template <int SPLIT>
__global__ __launch_bounds__(256) void add_ln_t(
    const float* __restrict__ a, const float* __restrict__ b,
    const float* __restrict__ g, const float* __restrict__ beta,
    float* __restrict__ out, __nv_bfloat16* __restrict__ hi,
    __nv_bfloat16* __restrict__ lo)
{
    const int n = blockIdx.x, tid = threadIdx.x;
    const size_t base = (size_t)n * D_;

    float v[3], s = 0.f, ss = 0.f;
#pragma unroll
    for (int t = 0; t < 3; t++) {
        int c = tid + t * 256;
        float x = a[base + c] + b[base + c];
        v[t] = x; s += x; ss += x * x;
    }
#pragma unroll
    for (int off = 16; off > 0; off >>= 1) {
        s  += __shfl_xor_sync(0xffffffffu, s,  off);
        ss += __shfl_xor_sync(0xffffffffu, ss, off);
    }
    __shared__ float sh_s[8], sh_ss[8];
    const int wid = tid >> 5, lane = tid & 31;
    if (lane == 0) { sh_s[wid] = s; sh_ss[wid] = ss; }
    __syncthreads();
    s = 0.f; ss = 0.f;
#pragma unroll
    for (int w = 0; w < 8; w++) { s += sh_s[w]; ss += sh_ss[w]; }

    const float mu  = s * (1.0f / D_);
    const float var = ss * (1.0f / D_) - mu * mu;
    const float r   = rsqrtf(var + EPSLN);
#pragma unroll
    for (int t = 0; t < 3; t++) {
        int c = tid + t * 256;
        float y = (v[t] - mu) * r * g[c] + beta[c];
        out[base + c] = y;
        if (SPLIT) {
            __nv_bfloat16 hh = __float2bfloat16(y);
            hi[base + c] = hh;
            lo[base + c] = __float2bfloat16(y - __bfloat162float(hh));
        }
    }
}

// ---------------------------------------------------------------------------
extern "C" void kernel_launch(void* const* d_in, const int* in_sizes, int n_in,
                              void* d_out, int out_size)
{
    const float* x     = (const float*)d_in[0];
    const float* w_row = (const float*)d_in[1];
    const float* b_row = (const float*)d_in[2];
    const float* w_col = (const float*)d_in[3];
    const float* b_col = (const float*)d_in[4];
    const float* g1    = (const float*)d_in[5];
    const float* beta1 = (const float*)d_in[6];
    const float* g2    = (const float*)d_in[7];
    const float* beta2 = (const float*)d_in[8];
    const int*   pmask = (const int*)d_in[9];
    float* out = (float*)d_out;

    float *qkv, *tmp;
    cudaGetSymbolAddress((void**)&qkv, g_qkv);
    cudaGetSymbolAddress((void**)&tmp, g_tmp);
    __nv_bfloat16 *ah, *al, *wrh, *wrl, *wch, *wcl;
    cudaGetSymbolAddress((void**)&ah,  g_ah);
    cudaGetSymbolAddress((void**)&al,  g_al);
    cudaGetSymbolAddress((void**)&wrh, g_wrh);
    cudaGetSymbolAddress((void**)&wrl, g_wrl);
    cudaGetSymbolAddress((void**)&wch, g_wch);
    cudaGetSymbolAddress((void**)&wcl, g_wcl);

    cudaFuncSetAttribute(gemm_hmma_x3, cudaFuncAttributeMaxDynamicSharedMemorySize, SMEM_GEMM);
    cudaFuncSetAttribute(attn_mma<2>, cudaFuncAttributeMaxDynamicSharedMemorySize, SMEM_ATT_ROW);
    cudaFuncSetAttribute(attn_mma<1>, cudaFuncAttributeMaxDynamicSharedMemorySize, SMEM_ATT_COL);

    const int nx = N_ * D_;
    const int nw = D3_ * D_;
    dim3 gemm_grid(GM / 128, N_ / 128);

    // splits (weights + x)
    split_f32<<<nw / 1024, 256>>>(w_row, wrh, wrl, nw);
    split_f32<<<nw / 1024, 256>>>(w_col, wch, wcl, nw);
    split_f32<<<nx / 1024, 256>>>(x, ah, al, nx);

    // ---- row pass ----
    gemm_hmma_x3<<<gemm_grid, 256, SMEM_GEMM>>>(ah, al, wrh, wrl, b_row, qkv);
    attn_mma<2><<<dim3(H_, E_), 256, SMEM_ATT_ROW>>>(qkv, pmask, tmp, 0);
    add_ln_t<1><<<N_, 256>>>(x, tmp, g1, beta1, out, ah, al);   // fused split

    // ---- column pass ----
    gemm_hmma_x3<<<gemm_grid, 256, SMEM_GEMM>>>(ah, al, wch, wcl, b_col, qkv);
    attn_mma<1><<<dim3(H_, L_), 256, SMEM_ATT_COL>>>(qkv, pmask, tmp, 1);
    add_ln_t<0><<<N_, 256>>>(out, tmp, g2, beta2, out, nullptr, nullptr);
}

// round 13
// speedup vs baseline: 5.4986x; 1.0460x over previous
#include <cuda_runtime.h>
#include <cuda_bf16.h>
#include <cstdint>

// Fixed problem shapes
#define B_  1
#define E_  128
#define L_  256
#define H_  12
#define DH_ 64
#define D_  768          // H_*DH_
#define D3_ 2304         // 3*D_
#define N_  32768        // B_*E_*L_
#define EPSLN 1e-5f
#define NEGV  -10000.0f

// Scratch (allocations forbidden -> device globals)
__device__ float g_qkv[(size_t)N_ * D3_];            // 302 MB; aliased as 2x bf16 [N,D3]
__device__ float g_tmp[(size_t)N_ * D_];             // 100 MB
__device__ __nv_bfloat16 g_ah[(size_t)N_ * D_];
__device__ __nv_bfloat16 g_al[(size_t)N_ * D_];
__device__ __nv_bfloat16 g_wrh[(size_t)D3_ * D_];
__device__ __nv_bfloat16 g_wrl[(size_t)D3_ * D_];
__device__ __nv_bfloat16 g_wch[(size_t)D3_ * D_];
__device__ __nv_bfloat16 g_wcl[(size_t)D3_ * D_];

// ---------------------------------------------------------------------------
// arch-agnostic PTX helpers
// ---------------------------------------------------------------------------
__device__ __forceinline__ uint32_t smem_u32(const void* p) {
    uint32_t a;
    asm("{ .reg .u64 t; cvta.to.shared.u64 t, %1; cvt.u32.u64 %0, t; }" : "=r"(a) : "l"(p));
    return a;
}
__device__ __forceinline__ void cp16(uint32_t s, const void* g) {
    asm volatile("cp.async.cg.shared.global [%0], [%1], 16;" :: "r"(s), "l"(g) : "memory");
}
__device__ __forceinline__ void cp_commit() {
    asm volatile("cp.async.commit_group;" ::: "memory");
}
template <int N>
__device__ __forceinline__ void cp_wait() {
    asm volatile("cp.async.wait_group %0;" :: "n"(N) : "memory");
}
__device__ __forceinline__ void ldsm4(uint32_t* r, uint32_t a) {
    asm volatile("ldmatrix.sync.aligned.m8n8.x4.shared.b16 {%0,%1,%2,%3}, [%4];"
                 : "=r"(r[0]), "=r"(r[1]), "=r"(r[2]), "=r"(r[3]) : "r"(a));
}
__device__ __forceinline__ void ldsm2t(uint32_t* r, uint32_t a) {
    asm volatile("ldmatrix.sync.aligned.m8n8.x2.trans.shared.b16 {%0,%1}, [%2];"
                 : "=r"(r[0]), "=r"(r[1]) : "r"(a));
}
__device__ __forceinline__ void mma16816(float* d, const uint32_t* a, const uint32_t* b) {
    asm volatile(
        "mma.sync.aligned.m16n8k16.row.col.f32.bf16.bf16.f32 "
        "{%0,%1,%2,%3}, {%4,%5,%6,%7}, {%8,%9}, {%0,%1,%2,%3};"
        : "+f"(d[0]), "+f"(d[1]), "+f"(d[2]), "+f"(d[3])
        : "r"(a[0]), "r"(a[1]), "r"(a[2]), "r"(a[3]), "r"(b[0]), "r"(b[1]));
}
__device__ __forceinline__ uint32_t pack2(__nv_bfloat16 a, __nv_bfloat16 b) {
    __nv_bfloat162 t = __halves2bfloat162(a, b);
    return *reinterpret_cast<uint32_t*>(&t);
}
__device__ __forceinline__ uint32_t sw128(uint32_t off) {
    return off ^ ((off >> 3) & 0x70);
}

// ---------------------------------------------------------------------------
// split: fp32 -> bf16 hi + bf16 lo
// ---------------------------------------------------------------------------
__global__ __launch_bounds__(256) void split_f32(
    const float* __restrict__ in, __nv_bfloat16* __restrict__ hi,
    __nv_bfloat16* __restrict__ lo, int n)
{
    int i = (blockIdx.x * 256 + threadIdx.x) * 4;
    if (i >= n) return;
    float4 v = *(const float4*)(in + i);
    float f[4] = {v.x, v.y, v.z, v.w};
    __nv_bfloat16 h[4], l[4];
#pragma unroll
    for (int q = 0; q < 4; q++) {
        h[q] = __float2bfloat16(f[q]);
        l[q] = __float2bfloat16(f[q] - __bfloat162float(h[q]));
    }
    *(__nv_bfloat162*)(hi + i)     = __halves2bfloat162(h[0], h[1]);
    *(__nv_bfloat162*)(hi + i + 2) = __halves2bfloat162(h[2], h[3]);
    *(__nv_bfloat162*)(lo + i)     = __halves2bfloat162(l[0], l[1]);
    *(__nv_bfloat162*)(lo + i + 2) = __halves2bfloat162(l[2], l[3]);
}

// ---------------------------------------------------------------------------
// bf16 3-way-split GEMM via mma.sync. Epilogue writes bf16 hi/lo split C.
// ---------------------------------------------------------------------------
#define GK 768
#define GM 2304
#define BKC 32
#define NIT 24
#define ABUF_B 16384
#define STG_B  (2 * ABUF_B)
#define SMEM_GEMM (3 * STG_B + 1024)

__device__ __forceinline__ void issue_stage3(
    uint32_t sbase, int kc,
    const __nv_bfloat16* __restrict__ pAh, const __nv_bfloat16* __restrict__ pAl,
    const __nv_bfloat16* __restrict__ pBh, const __nv_bfloat16* __restrict__ pBl,
    int tid)
{
#pragma unroll
    for (int i = 0; i < 4; i++) {
        int idx = i * 256 + tid;
        int r = idx >> 3, half = (idx >> 2) & 1, c16 = idx & 3;
        const __nv_bfloat16* g = (half ? pAl : pAh) + (size_t)r * GK + kc + c16 * 8;
        uint32_t off = (uint32_t)(r * 128 + half * 64 + c16 * 16);
        cp16(sbase + sw128(off), g);
    }
#pragma unroll
    for (int i = 0; i < 4; i++) {
        int idx = i * 256 + tid;
        int r = idx >> 3, half = (idx >> 2) & 1, c16 = idx & 3;
        const __nv_bfloat16* g = (half ? pBl : pBh) + (size_t)r * GK + kc + c16 * 8;
        uint32_t off = (uint32_t)(r * 128 + half * 64 + c16 * 16);
        cp16(sbase + ABUF_B + sw128(off), g);
    }
    cp_commit();
}

__global__ __launch_bounds__(256, 2) void gemm_hmma_x3(
    const __nv_bfloat16* __restrict__ Ah, const __nv_bfloat16* __restrict__ Al,
    const __nv_bfloat16* __restrict__ Bh, const __nv_bfloat16* __restrict__ Bl,
    const float* __restrict__ bias,
    __nv_bfloat16* __restrict__ Ch, __nv_bfloat16* __restrict__ Cl)
{
    extern __shared__ char dynsm[];
    uint32_t smb = smem_u32(dynsm);
    smb = (smb + 1023u) & ~1023u;

    const int tid  = threadIdx.x;
    const int wid  = tid >> 5, lane = tid & 31;
    const int wm   = wid >> 2;
    const int wn   = wid & 3;
    const int tileN = blockIdx.x;
    const int tileM = blockIdx.y;

    const __nv_bfloat16* pA0 = Ah + (size_t)tileM * 128 * GK;
    const __nv_bfloat16* pA1 = Al + (size_t)tileM * 128 * GK;
    const __nv_bfloat16* pB0 = Bh + (size_t)tileN * 128 * GK;
    const __nv_bfloat16* pB1 = Bl + (size_t)tileN * 128 * GK;

    issue_stage3(smb + 0 * STG_B, 0 * BKC, pA0, pA1, pB0, pB1, tid);
    issue_stage3(smb + 1 * STG_B, 1 * BKC, pA0, pA1, pB0, pB1, tid);

    float acc[4][4][4];
#pragma unroll
    for (int a = 0; a < 4; a++)
#pragma unroll
        for (int b = 0; b < 4; b++)
#pragma unroll
            for (int c = 0; c < 4; c++) acc[a][b][c] = 0.f;

    const int aRow  = lane & 15;
    const int aColB = (lane >> 4) * 16;
    const int grp   = lane >> 3;
    const int bRow  = ((grp >> 1) * 8) + (lane & 7);
    const int bColB = (grp & 1) * 16;

    int st = 0;
    for (int it = 0; it < NIT; it++) {
        if (it < NIT - 2) cp_wait<1>(); else cp_wait<0>();
        __syncthreads();

        if (it + 2 < NIT) {
            int stn = st + 2; if (stn >= 3) stn -= 3;
            issue_stage3(smb + (uint32_t)stn * STG_B, (it + 2) * BKC,
                         pA0, pA1, pB0, pB1, tid);
        }

        const uint32_t sA = smb + (uint32_t)st * STG_B;
        const uint32_t sB = sA + ABUF_B;

#pragma unroll
        for (int ks = 0; ks < 2; ks++) {
            const int kb = ks * 32;
            uint32_t ah[4][4], al4[4][4], bh4[2][4], bl4[2][4];
#pragma unroll
            for (int mt = 0; mt < 4; mt++) {
                uint32_t off = (uint32_t)((wm * 64 + mt * 16 + aRow) * 128 + kb + aColB);
                ldsm4(ah[mt],  sA + sw128(off));
                ldsm4(al4[mt], sA + sw128(off + 64));
            }
#pragma unroll
            for (int pr = 0; pr < 2; pr++) {
                uint32_t off = (uint32_t)((wn * 32 + pr * 16 + bRow) * 128 + kb + bColB);
                ldsm4(bh4[pr], sB + sw128(off));
                ldsm4(bl4[pr], sB + sw128(off + 64));
            }
#pragma unroll
            for (int mt = 0; mt < 4; mt++)
#pragma unroll
                for (int pr = 0; pr < 2; pr++)
#pragma unroll
                    for (int half = 0; half < 2; half++) {
                        const int nt = pr * 2 + half;
                        mma16816(acc[mt][nt], ah[mt],  &bh4[pr][half * 2]);
                        mma16816(acc[mt][nt], ah[mt],  &bl4[pr][half * 2]);
                        mma16816(acc[mt][nt], al4[mt], &bh4[pr][half * 2]);
                    }
        }
        st++; if (st == 3) st = 0;
    }

    const int r0 = tileM * 128 + wm * 64 + (lane >> 2);
    const int c0 = tileN * 128 + wn * 32 + (lane & 3) * 2;
#pragma unroll
    for (int mt = 0; mt < 4; mt++) {
#pragma unroll
        for (int nt = 0; nt < 4; nt++) {
            const int row = r0 + mt * 16;
            const int col = c0 + nt * 8;
            const float b0 = bias[col], b1 = bias[col + 1];
#pragma unroll
            for (int rr = 0; rr < 2; rr++) {
                float y0 = acc[mt][nt][rr * 2 + 0] + b0;
                float y1 = acc[mt][nt][rr * 2 + 1] + b1;
                __nv_bfloat16 h0 = __float2bfloat16(y0);
                __nv_bfloat16 h1 = __float2bfloat16(y1);
                __nv_bfloat16 l0 = __float2bfloat16(y0 - __bfloat162float(h0));
                __nv_bfloat16 l1 = __float2bfloat16(y1 - __bfloat162float(h1));
                size_t p = (size_t)(row + rr * 8) * GM + col;
                *(__nv_bfloat162*)(Ch + p) = __halves2bfloat162(h0, h1);
                *(__nv_bfloat162*)(Cl + p) = __halves2bfloat162(l0, l1);
            }
        }
    }
}

// ---------------------------------------------------------------------------
// Flash-style HMMA attention, bf16 hi/lo qkv inputs (no in-kernel splits).
// Q/K/V staged via cp.async into SW128 128B-row tiles; 3-stage K/V pipeline.
//   row pass: MT=2, grid (12, 128), base = e*256, step = 1
//   col pass: MT=1, grid (12, 256), base = l,     step = 256
// ---------------------------------------------------------------------------
#define CH_TILE 8192                 // 64 rows x 128B
#define CH_STG  (4 * CH_TILE)        // Kh,Kl,Vh,Vl = 32 KB

template <int MT>
__global__ __launch_bounds__(256, 1) void attn_mma(
    const __nv_bfloat16* __restrict__ qh, const __nv_bfloat16* __restrict__ ql,
    const int* __restrict__ mask, float* __restrict__ out, int colmode)
{
    constexpr int NQ  = MT * 128;
    constexpr int NCH = MT * 2;
    extern __shared__ __align__(128) char smraw[];
    const uint32_t uQh = smem_u32(smraw);
    const uint32_t uQl = uQh + NQ * 128;
    const uint32_t uST = uQl + NQ * 128;
    float* negs = (float*)(smraw + 2 * NQ * 128 + 3 * CH_STG);

    const int tid  = threadIdx.x;
    const int wid  = tid >> 5, lane = tid & 31;
    const int h    = blockIdx.x;
    const int base = colmode ? (int)blockIdx.y : (int)blockIdx.y * 256;
    const int step = colmode ? 256 : 1;

    // issue Q tiles (hi+lo)
#pragma unroll
    for (int i = 0; i < NQ / 16; i++) {
        int idx = i * 256 + tid;                 // 0 .. NQ*16-1
        int t = (idx >= NQ * 8);
        int r = (idx >> 3) & (NQ - 1);
        int c = idx & 7;
        const __nv_bfloat16* src = (t ? ql : qh) + (size_t)(base + r * step) * D3_ + h * 64 + c * 8;
        cp16((t ? uQl : uQh) + sw128((uint32_t)(r * 128 + c * 16)), src);
    }
    cp_commit();
    for (int i = tid; i < NQ; i += 256)
        negs[i] = mask[base + i * step] ? NEGV : 0.f;

    auto issue_ch = [&](int ch) {
        uint32_t sb = uST + (uint32_t)(ch % 3) * CH_STG;
#pragma unroll
        for (int i = 0; i < 8; i++) {
            int idx = i * 256 + tid;             // 0..2047
            int tile = idx >> 9;                 // Kh,Kl,Vh,Vl
            int r = (idx >> 3) & 63;
            int c = idx & 7;
            const __nv_bfloat16* bp = (tile & 1) ? ql : qh;
            int coff = (tile >= 2) ? 1536 : 768;
            const __nv_bfloat16* src = bp + (size_t)(base + (ch * 64 + r) * step) * D3_
                                       + coff + h * 64 + c * 8;
            cp16(sb + (uint32_t)tile * CH_TILE + sw128((uint32_t)(r * 128 + c * 16)), src);
        }
        cp_commit();
    };
    issue_ch(0);
    if (NCH > 1) issue_ch(1);

    float s[MT][8][4], o[MT][8][4], mrow[MT][2], lrow[MT][2];
#pragma unroll
    for (int mt = 0; mt < MT; mt++) {
        mrow[mt][0] = mrow[mt][1] = -1e30f;
        lrow[mt][0] = lrow[mt][1] = 0.f;
#pragma unroll
        for (int nt = 0; nt < 8; nt++)
#pragma unroll
            for (int c = 0; c < 4; c++) o[mt][nt][c] = 0.f;
    }

    const int aRow  = lane & 15;
    const int aColB = (lane >> 4) * 16;
    const int grp   = lane >> 3;
    const int bRow4 = ((grp >> 1) * 8) + (lane & 7);
    const int bColB4 = (grp & 1) * 16;

    for (int ch = 0; ch < NCH; ch++) {
        if (ch < NCH - 1) cp_wait<1>(); else cp_wait<0>();
        __syncthreads();
        if (ch + 2 < NCH) issue_ch(ch + 2);

        const uint32_t sK = uST + (uint32_t)(ch % 3) * CH_STG;   // Kh base

#pragma unroll
        for (int mt = 0; mt < MT; mt++)
#pragma unroll
            for (int nt = 0; nt < 8; nt++)
#pragma unroll
                for (int c = 0; c < 4; c++) s[mt][nt][c] = 0.f;

        // S = Q K^T
#pragma unroll
        for (int kq = 0; kq < 4; kq++) {
            uint32_t ah[MT][4], al[MT][4];
#pragma unroll
            for (int mt = 0; mt < MT; mt++) {
                uint32_t off = (uint32_t)((wid * (MT * 16) + mt * 16 + aRow) * 128
                                          + kq * 32 + aColB);
                ldsm4(ah[mt], uQh + sw128(off));
                ldsm4(al[mt], uQl + sw128(off));
            }
            uint32_t kh4[4][4], kl4[4][4];
#pragma unroll
            for (int pr = 0; pr < 4; pr++) {
                uint32_t off = (uint32_t)((pr * 16 + bRow4) * 128 + kq * 32 + bColB4);
                ldsm4(kh4[pr], sK + sw128(off));
                ldsm4(kl4[pr], sK + CH_TILE + sw128(off));
            }
#pragma unroll
            for (int mt = 0; mt < MT; mt++)
#pragma unroll
                for (int pr = 0; pr < 4; pr++)
#pragma unroll
                    for (int half = 0; half < 2; half++) {
                        const int nt = pr * 2 + half;
                        mma16816(s[mt][nt], ah[mt], &kh4[pr][half * 2]);
                        mma16816(s[mt][nt], ah[mt], &kl4[pr][half * 2]);
                        mma16816(s[mt][nt], al[mt], &kh4[pr][half * 2]);
                    }
        }

        // scale + mask:  s = s*DH^-0.5 + neg
#pragma unroll
        for (int nt = 0; nt < 8; nt++) {
            int j = ch * 64 + nt * 8 + (lane & 3) * 2;
            float n0 = negs[j], n1 = negs[j + 1];
#pragma unroll
            for (int mt = 0; mt < MT; mt++) {
                s[mt][nt][0] = s[mt][nt][0] * 0.125f + n0;
                s[mt][nt][1] = s[mt][nt][1] * 0.125f + n1;
                s[mt][nt][2] = s[mt][nt][2] * 0.125f + n0;
                s[mt][nt][3] = s[mt][nt][3] * 0.125f + n1;
            }
        }
        // online softmax
#pragma unroll
        for (int mt = 0; mt < MT; mt++) {
#pragma unroll
            for (int hf = 0; hf < 2; hf++) {
                float rm = -1e30f;
#pragma unroll
                for (int nt = 0; nt < 8; nt++)
                    rm = fmaxf(rm, fmaxf(s[mt][nt][2 * hf], s[mt][nt][2 * hf + 1]));
                rm = fmaxf(rm, __shfl_xor_sync(0xffffffffu, rm, 1));
                rm = fmaxf(rm, __shfl_xor_sync(0xffffffffu, rm, 2));
                float mo = mrow[mt][hf];
                float mn = fmaxf(mo, rm);
                float corr = __expf(mo - mn);
                float rs = 0.f;
#pragma unroll
                for (int nt = 0; nt < 8; nt++) {
                    float p0 = __expf(s[mt][nt][2 * hf]     - mn);
                    float p1 = __expf(s[mt][nt][2 * hf + 1] - mn);
                    s[mt][nt][2 * hf] = p0; s[mt][nt][2 * hf + 1] = p1;
                    rs += p0 + p1;
                    o[mt][nt][2 * hf] *= corr; o[mt][nt][2 * hf + 1] *= corr;
                }
                rs += __shfl_xor_sync(0xffffffffu, rs, 1);
                rs += __shfl_xor_sync(0xffffffffu, rs, 2);
                lrow[mt][hf] = lrow[mt][hf] * corr + rs;
                mrow[mt][hf] = mn;
            }
        }

        // O += P V
#pragma unroll
        for (int kk = 0; kk < 4; kk++) {
            uint32_t pah[MT][4], pal[MT][4];
#pragma unroll
            for (int mt = 0; mt < MT; mt++) {
#pragma unroll
                for (int q = 0; q < 4; q++) {
                    int nt = kk * 2 + (q >> 1);
                    int i0 = (q & 1) * 2;
                    float p0 = s[mt][nt][i0], p1 = s[mt][nt][i0 + 1];
                    __nv_bfloat16 h0 = __float2bfloat16(p0);
                    __nv_bfloat16 h1 = __float2bfloat16(p1);
                    pah[mt][q] = pack2(h0, h1);
                    __nv_bfloat16 l0 = __float2bfloat16(p0 - __bfloat162float(h0));
                    __nv_bfloat16 l1 = __float2bfloat16(p1 - __bfloat162float(h1));
                    pal[mt][q] = pack2(l0, l1);
                }
            }
#pragma unroll
            for (int nt = 0; nt < 8; nt++) {
                uint32_t vbh[2], vbl[2];
                uint32_t voff = sw128((uint32_t)((kk * 16 + (lane & 15)) * 128 + nt * 16));
                ldsm2t(vbh, sK + 2 * CH_TILE + voff);
                ldsm2t(vbl, sK + 3 * CH_TILE + voff);
#pragma unroll
                for (int mt = 0; mt < MT; mt++) {
                    mma16816(o[mt][nt], pah[mt], vbh);
                    mma16816(o[mt][nt], pah[mt], vbl);
                    mma16816(o[mt][nt], pal[mt], vbh);
                }
            }
        }
    }

#pragma unroll
    for (int mt = 0; mt < MT; mt++) {
#pragma unroll
        for (int hf = 0; hf < 2; hf++) {
            float inv = 1.f / lrow[mt][hf];
            int qrow = wid * (MT * 16) + mt * 16 + hf * 8 + (lane >> 2);
            size_t ob = (size_t)(base + qrow * step) * D_ + h * 64 + (lane & 3) * 2;
#pragma unroll
            for (int nt = 0; nt < 8; nt++) {
                float2 v = {o[mt][nt][2 * hf] * inv, o[mt][nt][2 * hf + 1] * inv};
                *(float2*)(out + ob + nt * 8) = v;
            }
        }
    }
}

#define SMEM_ATT_ROW (2 * 256 * 128 + 3 * CH_STG + 256 * 4)   // 164 KB
#define SMEM_ATT_COL (2 * 128 * 128 + 3 * CH_STG + 128 * 4)   // 132 KB

// ---------------------------------------------------------------------------
// out = LayerNorm(a + b) * g + beta, optionally also emit bf16 hi/lo split
// ---------------------------------------------------------------------------
template <int SPLIT>
__global__ __launch_bounds__(256) void add_ln_t(
    const float* __restrict__ a, const float* __restrict__ b,
    const float* __restrict__ g, const float* __restrict__ beta,
    float* __restrict__ out, __nv_bfloat16* __restrict__ hi,
    __nv_bfloat16* __restrict__ lo)
{
    const int n = blockIdx.x, tid = threadIdx.x;
    const size_t base = (size_t)n * D_;

    float v[3], s = 0.f, ss = 0.f;
#pragma unroll
    for (int t = 0; t < 3; t++) {
        int c = tid + t * 256;
        float x = a[base + c] + b[base + c];
        v[t] = x; s += x; ss += x * x;
    }
#pragma unroll
    for (int off = 16; off > 0; off >>= 1) {
        s  += __shfl_xor_sync(0xffffffffu, s,  off);
        ss += __shfl_xor_sync(0xffffffffu, ss, off);
    }
    __shared__ float sh_s[8], sh_ss[8];
    const int wid = tid >> 5, lane = tid & 31;
    if (lane == 0) { sh_s[wid] = s; sh_ss[wid] = ss; }
    __syncthreads();
    s = 0.f; ss = 0.f;
#pragma unroll
    for (int w = 0; w < 8; w++) { s += sh_s[w]; ss += sh_ss[w]; }

    const float mu  = s * (1.0f / D_);
    const float var = ss * (1.0f / D_) - mu * mu;
    const float r   = rsqrtf(var + EPSLN);
#pragma unroll
    for (int t = 0; t < 3; t++) {
        int c = tid + t * 256;
        float y = (v[t] - mu) * r * g[c] + beta[c];
        out[base + c] = y;
        if (SPLIT) {
            __nv_bfloat16 hh = __float2bfloat16(y);
            hi[base + c] = hh;
            lo[base + c] = __float2bfloat16(y - __bfloat162float(hh));
        }
    }
}

// ---------------------------------------------------------------------------
extern "C" void kernel_launch(void* const* d_in, const int* in_sizes, int n_in,
                              void* d_out, int out_size)
{
    const float* x     = (const float*)d_in[0];
    const float* w_row = (const float*)d_in[1];
    const float* b_row = (const float*)d_in[2];
    const float* w_col = (const float*)d_in[3];
    const float* b_col = (const float*)d_in[4];
    const float* g1    = (const float*)d_in[5];
    const float* beta1 = (const float*)d_in[6];
    const float* g2    = (const float*)d_in[7];
    const float* beta2 = (const float*)d_in[8];
    const int*   pmask = (const int*)d_in[9];
    float* out = (float*)d_out;

    float *qkv, *tmp;
    cudaGetSymbolAddress((void**)&qkv, g_qkv);
    cudaGetSymbolAddress((void**)&tmp, g_tmp);
    __nv_bfloat16 *ah, *al, *wrh, *wrl, *wch, *wcl;
    cudaGetSymbolAddress((void**)&ah,  g_ah);
    cudaGetSymbolAddress((void**)&al,  g_al);
    cudaGetSymbolAddress((void**)&wrh, g_wrh);
    cudaGetSymbolAddress((void**)&wrl, g_wrl);
    cudaGetSymbolAddress((void**)&wch, g_wch);
    cudaGetSymbolAddress((void**)&wcl, g_wcl);

    // alias the fp32 qkv buffer as two bf16 [N, D3] arrays
    __nv_bfloat16* qkvh = (__nv_bfloat16*)qkv;
    __nv_bfloat16* qkvl = qkvh + (size_t)N_ * D3_;

    cudaFuncSetAttribute(gemm_hmma_x3, cudaFuncAttributeMaxDynamicSharedMemorySize, SMEM_GEMM);
    cudaFuncSetAttribute(attn_mma<2>, cudaFuncAttributeMaxDynamicSharedMemorySize, SMEM_ATT_ROW);
    cudaFuncSetAttribute(attn_mma<1>, cudaFuncAttributeMaxDynamicSharedMemorySize, SMEM_ATT_COL);

    const int nx = N_ * D_;
    const int nw = D3_ * D_;
    dim3 gemm_grid(GM / 128, N_ / 128);

    // splits (weights + x)
    split_f32<<<nw / 1024, 256>>>(w_row, wrh, wrl, nw);
    split_f32<<<nw / 1024, 256>>>(w_col, wch, wcl, nw);
    split_f32<<<nx / 1024, 256>>>(x, ah, al, nx);

    // ---- row pass ----
    gemm_hmma_x3<<<gemm_grid, 256, SMEM_GEMM>>>(ah, al, wrh, wrl, b_row, qkvh, qkvl);
    attn_mma<2><<<dim3(H_, E_), 256, SMEM_ATT_ROW>>>(qkvh, qkvl, pmask, tmp, 0);
    add_ln_t<1><<<N_, 256>>>(x, tmp, g1, beta1, out, ah, al);

    // ---- column pass ----
    gemm_hmma_x3<<<gemm_grid, 256, SMEM_GEMM>>>(ah, al, wch, wcl, b_col, qkvh, qkvl);
    attn_mma<1><<<dim3(H_, L_), 256, SMEM_ATT_COL>>>(qkvh, qkvl, pmask, tmp, 1);
    add_ln_t<0><<<N_, 256>>>(out, tmp, g2, beta2, out, nullptr, nullptr);
}